// round 1
// baseline (speedup 1.0000x reference)
#include <cuda_runtime.h>

// Problem constants
#define NN   4
#define CC   256
#define OO   256
#define HH   96
#define WW   96
#define HW   9216            // 96*96
#define NHW  36864           // 4*9216
#define KDIM 2304            // 256*9

// GEMM tiling
#define BM   128
#define BN   256
#define BK   16
#define NTHR 512

// ---------------- scratch (static device globals; no allocation) ----------------
__device__ float g_off[NN * 18 * HW];          // offset conv output  (2.65 MB)
__device__ float g_Wr[KDIM * OO];              // reordered DCN weights (2.36 MB)
__device__ float g_y[NN * OO * HW];            // pre-BN GEMM output  (37.7 MB)
__device__ float g_sum[OO];
__device__ float g_sq[OO];
__device__ float g_scale[OO];
__device__ float g_shift[OO];

// ---------------- packed f32x2 helpers (FFMA2 — ptxas never emits from C++) ----
__device__ __forceinline__ unsigned long long pack2(float x, float y) {
    unsigned long long r;
    asm("mov.b64 %0, {%1, %2};" : "=l"(r) : "f"(x), "f"(y));
    return r;
}
__device__ __forceinline__ void unpack2(unsigned long long v, float &x, float &y) {
    asm("mov.b64 {%0, %1}, %2;" : "=f"(x), "=f"(y) : "l"(v));
}
__device__ __forceinline__ void ffma2(unsigned long long &d,
                                      unsigned long long a,
                                      unsigned long long b) {
    asm("fma.rn.f32x2 %0, %1, %2, %0;" : "+l"(d) : "l"(a), "l"(b));
}

// ---------------- kernel 1: zero BN accumulators ----------------
__global__ void zero_stats_kernel() {
    g_sum[threadIdx.x] = 0.f;
    g_sq[threadIdx.x]  = 0.f;
}

// ---------------- kernel 2: reorder w_dcn[o,c,k] -> Wr[(k*256+c), o] ----------
__global__ void reorder_w_kernel(const float* __restrict__ w_dcn) {
    int e = blockIdx.x * blockDim.x + threadIdx.x;   // < 589824
    int kc = e >> 8, o = e & 255;
    int k  = kc >> 8, c = kc & 255;
    g_Wr[e] = w_dcn[(o * CC + c) * 9 + k];
}

// ---------------- kernel 3: offset conv (3x3, C=256 -> 18) ----------------
__global__ __launch_bounds__(256) void offset_conv_kernel(
    const float* __restrict__ x,
    const float* __restrict__ w_off,
    const float* __restrict__ b_off)
{
    __shared__ float xs[18][19];
    __shared__ float ws[162];
    int n  = blockIdx.z;
    int h0 = blockIdx.y * 16, w0 = blockIdx.x * 16;
    int tid = threadIdx.x;
    int ty = tid >> 4, tx = tid & 15;

    float acc[18];
#pragma unroll
    for (int i = 0; i < 18; i++) acc[i] = 0.f;

    for (int c = 0; c < CC; c++) {
        // load 18x18 halo tile (zero-padded)
        for (int i = tid; i < 324; i += 256) {
            int r = i / 18, q = i - r * 18;
            int hh = h0 - 1 + r, wp = w0 - 1 + q;
            float v = 0.f;
            if ((unsigned)hh < (unsigned)HH && (unsigned)wp < (unsigned)WW)
                v = x[((n * CC + c) * HH + hh) * WW + wp];
            xs[r][q] = v;
        }
        // weights for this channel: 18 outputs x 9 taps
        if (tid < 162) {
            int oc = tid / 9, t = tid - oc * 9;
            ws[tid] = w_off[(oc * CC + c) * 9 + t];
        }
        __syncthreads();

        float xv[9];
#pragma unroll
        for (int t = 0; t < 9; t++) xv[t] = xs[ty + t / 3][tx + t % 3];
#pragma unroll
        for (int oc = 0; oc < 18; oc++) {
            float a = acc[oc];
#pragma unroll
            for (int t = 0; t < 9; t++) a = fmaf(ws[oc * 9 + t], xv[t], a);
            acc[oc] = a;
        }
        __syncthreads();
    }

    int h = h0 + ty, w = w0 + tx;
#pragma unroll
    for (int oc = 0; oc < 18; oc++)
        g_off[((n * 18 + oc) * HH + h) * WW + w] = acc[oc] + b_off[oc];
}

// ---------------- kernel 4: fused bilinear-gather implicit GEMM ----------------
// y[m, o] = sum_{k, c} sample(x; m, k, c) * Wr[k*256+c, o]
// block: BM=128 pixels x BN=256 outputs, 512 threads, 8x8 microtile (f32x2 packed).
__global__ __launch_bounds__(NTHR, 1) void dcn_gemm_kernel(const float* __restrict__ X)
{
    __shared__ __align__(16) float As[BK][BM];    // 8 KB
    __shared__ __align__(16) float Bs[BK][BN];    // 16 KB
    __shared__ int2   tI[BM][9];                  // 9 KB
    __shared__ float2 tF[BM][9];                  // 9 KB

    int tid  = threadIdx.x;
    int m0   = blockIdx.x * BM;
    int n    = m0 / HW;
    int pix0 = m0 - n * HW;

    // ---- build per-(pixel,k) sampling table ----
    for (int e = tid; e < BM * 9; e += NTHR) {
        int mi = e / 9, k = e - mi * 9;
        int pix = pix0 + mi;
        int h = pix / WW, w = pix - h * WW;
        float dy = g_off[((n * 18 + 2 * k) * HH + h) * WW + w];
        float dx = g_off[((n * 18 + 2 * k + 1) * HH + h) * WW + w];
        float py = (float)(h + k / 3 - 1) + dy;
        float px = (float)(w + (k % 3) - 1) + dx;
        float fy = floorf(py), fx = floorf(px);
        tI[mi][k] = make_int2((int)fy, (int)fx);
        tF[mi][k] = make_float2(py - fy, px - fx);
    }
    __syncthreads();

    unsigned long long acc[4][8];
#pragma unroll
    for (int a = 0; a < 4; a++)
#pragma unroll
        for (int b = 0; b < 8; b++) acc[a][b] = 0ull;

    int tm = tid & 15;          // 16 groups along M (8 rows each)
    int tn = tid >> 4;          // 32 groups along N (8 cols each)
    int mA  = tid & 127;        // A-fill pixel
    int clA = tid >> 7;         // A-fill c-sub 0..3
    const float* xn = X + (size_t)(n * CC) * HW;

    for (int k = 0; k < 9; k++) {
        // bilinear geometry for (mA, k): constant across the 16 c-chunks
        int2   ii = tI[mA][k];
        float2 ff = tF[mA][k];
        int y0 = ii.x, x0 = ii.y;
        float wy = ff.x, wx = ff.y;
        float w00 = (1.f - wy) * (1.f - wx);
        float w01 = (1.f - wy) * wx;
        float w10 = wy * (1.f - wx);
        float w11 = wy * wx;
        bool vy0 = (unsigned)y0       < (unsigned)HH;
        bool vy1 = (unsigned)(y0 + 1) < (unsigned)HH;
        bool vx0 = (unsigned)x0       < (unsigned)WW;
        bool vx1 = (unsigned)(x0 + 1) < (unsigned)WW;
        int yc0 = min(max(y0, 0), HH - 1), yc1 = min(max(y0 + 1, 0), HH - 1);
        int xc0 = min(max(x0, 0), WW - 1), xc1 = min(max(x0 + 1, 0), WW - 1);
        int i00 = yc0 * WW + xc0, i01 = yc0 * WW + xc1;
        int i10 = yc1 * WW + xc0, i11 = yc1 * WW + xc1;
        bool p00 = vy0 && vx0, p01 = vy0 && vx1, p10 = vy1 && vx0, p11 = vy1 && vx1;

        for (int sub = 0; sub < 16; sub++) {
            int c0 = sub << 4;
            // ---- fill B tile (16 x 256), coalesced ----
#pragma unroll
            for (int i = 0; i < 8; i++) {
                int e = tid + i * NTHR;
                int r = e >> 8, col = e & 255;
                Bs[r][col] = g_Wr[(k * 256 + c0 + r) * 256 + col];
            }
            // ---- fill A tile (16 x 128) via bilinear gather ----
            {
                const float* xb = xn + (size_t)(c0 + clA) * HW;
#pragma unroll
                for (int i = 0; i < 4; i++) {
                    float v00 = p00 ? xb[i00] : 0.f;
                    float v01 = p01 ? xb[i01] : 0.f;
                    float v10 = p10 ? xb[i10] : 0.f;
                    float v11 = p11 ? xb[i11] : 0.f;
                    As[clA + 4 * i][mA] =
                        fmaf(w00, v00, fmaf(w01, v01, fmaf(w10, v10, w11 * v11)));
                    xb += 4 * HW;
                }
            }
            __syncthreads();

            // ---- 8x8 microtile, f32x2-packed outer products ----
#pragma unroll
            for (int ccs = 0; ccs < BK; ccs++) {
                ulonglong2 aA = *(const ulonglong2*)&As[ccs][tm * 8];
                ulonglong2 aB = *(const ulonglong2*)&As[ccs][tm * 8 + 4];
                float4 b0 = *(const float4*)&Bs[ccs][tn * 8];
                float4 b1 = *(const float4*)&Bs[ccs][tn * 8 + 4];
                unsigned long long ap0 = aA.x, ap1 = aA.y, ap2 = aB.x, ap3 = aB.y;
                float bf[8] = {b0.x, b0.y, b0.z, b0.w, b1.x, b1.y, b1.z, b1.w};
#pragma unroll
                for (int j = 0; j < 8; j++) {
                    unsigned long long bb = pack2(bf[j], bf[j]);
                    ffma2(acc[0][j], ap0, bb);
                    ffma2(acc[1][j], ap1, bb);
                    ffma2(acc[2][j], ap2, bb);
                    ffma2(acc[3][j], ap3, bb);
                }
            }
            __syncthreads();
        }
    }

    // ---- epilogue: store y, accumulate BN stats ----
    float ls[8], lq[8];
#pragma unroll
    for (int j = 0; j < 8; j++) {
        float v[8];
#pragma unroll
        for (int mp = 0; mp < 4; mp++) unpack2(acc[mp][j], v[2 * mp], v[2 * mp + 1]);
        float s = 0.f, q = 0.f;
#pragma unroll
        for (int r = 0; r < 8; r++) { s += v[r]; q = fmaf(v[r], v[r], q); }
        ls[j] = s; lq[j] = q;
        int o = tn * 8 + j;
        float* yp = g_y + (size_t)(n * OO + o) * HW + pix0 + tm * 8;
        *(float4*)(yp)     = make_float4(v[0], v[1], v[2], v[3]);
        *(float4*)(yp + 4) = make_float4(v[4], v[5], v[6], v[7]);
    }
    // reduce across the 16 tm-lanes sharing the same o-set
#pragma unroll
    for (int j = 0; j < 8; j++) {
#pragma unroll
        for (int d = 8; d >= 1; d >>= 1) {
            ls[j] += __shfl_xor_sync(0xFFFFFFFFu, ls[j], d);
            lq[j] += __shfl_xor_sync(0xFFFFFFFFu, lq[j], d);
        }
    }
    if ((tid & 15) == 0) {
#pragma unroll
        for (int j = 0; j < 8; j++) {
            atomicAdd(&g_sum[tn * 8 + j], ls[j]);
            atomicAdd(&g_sq[tn * 8 + j],  lq[j]);
        }
    }
}

// ---------------- kernel 5: finalize BN stats ----------------
__global__ void finalize_kernel(const float* __restrict__ gamma,
                                const float* __restrict__ beta) {
    int o = threadIdx.x;
    const float inv_n = 1.f / (float)NHW;
    float m = g_sum[o] * inv_n;
    float v = g_sq[o] * inv_n - m * m;
    float a = v + 1e-5f;
    float is = rsqrtf(a);
    is = is * (1.5f - 0.5f * a * is * is);   // one Newton step
    float sc = is * gamma[o];
    g_scale[o] = sc;
    g_shift[o] = beta[o] - m * sc;
}

// ---------------- kernel 6: normalize + relu ----------------
__global__ void bn_relu_kernel(float* __restrict__ out) {
    int i = blockIdx.x * blockDim.x + threadIdx.x;
    int stride = gridDim.x * blockDim.x;
    const float4* y4 = (const float4*)g_y;
    float4* o4 = (float4*)out;
    const int total4 = NN * OO * HW / 4;       // 2359296
    for (; i < total4; i += stride) {
        int o = (i / (HW / 4)) & 255;
        float sc = g_scale[o], sh = g_shift[o];
        float4 v = y4[i];
        v.x = fmaxf(fmaf(v.x, sc, sh), 0.f);
        v.y = fmaxf(fmaf(v.y, sc, sh), 0.f);
        v.z = fmaxf(fmaf(v.z, sc, sh), 0.f);
        v.w = fmaxf(fmaf(v.w, sc, sh), 0.f);
        o4[i] = v;
    }
}

// ---------------- launch ----------------
extern "C" void kernel_launch(void* const* d_in, const int* in_sizes, int n_in,
                              void* d_out, int out_size) {
    const float* x     = (const float*)d_in[0];
    const float* w_off = (const float*)d_in[1];
    const float* b_off = (const float*)d_in[2];
    const float* w_dcn = (const float*)d_in[3];
    const float* gamma = (const float*)d_in[4];
    const float* beta  = (const float*)d_in[5];

    zero_stats_kernel<<<1, 256>>>();
    reorder_w_kernel<<<1152, 512>>>(w_dcn);                 // 589824 elems exact
    offset_conv_kernel<<<dim3(6, 6, NN), 256>>>(x, w_off, b_off);
    dcn_gemm_kernel<<<NHW / BM, NTHR>>>(x);                 // 288 blocks
    finalize_kernel<<<1, 256>>>(gamma, beta);
    bn_relu_kernel<<<2304, 256>>>((float*)d_out);
}

// round 4
// speedup vs baseline: 1.0011x; 1.0011x over previous
#include <cuda_runtime.h>

// Problem constants
#define NN   4
#define CC   256
#define OO   256
#define HH   96
#define WW   96
#define HW   9216            // 96*96
#define NHW  36864           // 4*9216
#define KDIM 2304            // 256*9

// GEMM tiling
#define BM   128
#define BN   256
#define BK   16
#define NTHR 512

// ---------------- scratch (static device globals; no allocation) ----------------
__device__ float g_off[NN * 18 * HW];          // offset conv output  (2.65 MB)
__device__ float g_Wr[KDIM * OO];              // reordered DCN weights (2.36 MB)
__device__ float g_y[NN * OO * HW];            // pre-BN GEMM output  (37.7 MB)
__device__ float g_sum[OO];
__device__ float g_sq[OO];
__device__ float g_scale[OO];
__device__ float g_shift[OO];

// ---------------- packed f32x2 helpers (FFMA2 — ptxas never emits from C++) ----
__device__ __forceinline__ unsigned long long pack2(float x, float y) {
    unsigned long long r;
    asm("mov.b64 %0, {%1, %2};" : "=l"(r) : "f"(x), "f"(y));
    return r;
}
__device__ __forceinline__ void unpack2(unsigned long long v, float &x, float &y) {
    asm("mov.b64 {%0, %1}, %2;" : "=f"(x), "=f"(y) : "l"(v));
}
__device__ __forceinline__ void ffma2(unsigned long long &d,
                                      unsigned long long a,
                                      unsigned long long b) {
    asm("fma.rn.f32x2 %0, %1, %2, %0;" : "+l"(d) : "l"(a), "l"(b));
}

// ---------------- kernel 1: zero BN accumulators ----------------
__global__ void zero_stats_kernel() {
    g_sum[threadIdx.x] = 0.f;
    g_sq[threadIdx.x]  = 0.f;
}

// ---------------- kernel 2: reorder w_dcn[o,c,k] -> Wr[(k*256+c), o] ----------
__global__ void reorder_w_kernel(const float* __restrict__ w_dcn) {
    int e = blockIdx.x * blockDim.x + threadIdx.x;   // < 589824
    int kc = e >> 8, o = e & 255;
    int k  = kc >> 8, c = kc & 255;
    g_Wr[e] = w_dcn[(o * CC + c) * 9 + k];
}

// ---------------- kernel 3: offset conv (3x3, C=256 -> 18) ----------------
__global__ __launch_bounds__(256) void offset_conv_kernel(
    const float* __restrict__ x,
    const float* __restrict__ w_off,
    const float* __restrict__ b_off)
{
    __shared__ float xs[18][19];
    __shared__ float ws[162];
    int n  = blockIdx.z;
    int h0 = blockIdx.y * 16, w0 = blockIdx.x * 16;
    int tid = threadIdx.x;
    int ty = tid >> 4, tx = tid & 15;

    float acc[18];
#pragma unroll
    for (int i = 0; i < 18; i++) acc[i] = 0.f;

    for (int c = 0; c < CC; c++) {
        // load 18x18 halo tile (zero-padded)
        for (int i = tid; i < 324; i += 256) {
            int r = i / 18, q = i - r * 18;
            int hh = h0 - 1 + r, wp = w0 - 1 + q;
            float v = 0.f;
            if ((unsigned)hh < (unsigned)HH && (unsigned)wp < (unsigned)WW)
                v = x[((n * CC + c) * HH + hh) * WW + wp];
            xs[r][q] = v;
        }
        // weights for this channel: 18 outputs x 9 taps
        if (tid < 162) {
            int oc = tid / 9, t = tid - oc * 9;
            ws[tid] = w_off[(oc * CC + c) * 9 + t];
        }
        __syncthreads();

        float xv[9];
#pragma unroll
        for (int t = 0; t < 9; t++) xv[t] = xs[ty + t / 3][tx + t % 3];
#pragma unroll
        for (int oc = 0; oc < 18; oc++) {
            float a = acc[oc];
#pragma unroll
            for (int t = 0; t < 9; t++) a = fmaf(ws[oc * 9 + t], xv[t], a);
            acc[oc] = a;
        }
        __syncthreads();
    }

    int h = h0 + ty, w = w0 + tx;
#pragma unroll
    for (int oc = 0; oc < 18; oc++)
        g_off[((n * 18 + oc) * HH + h) * WW + w] = acc[oc] + b_off[oc];
}

// ---------------- kernel 4: fused bilinear-gather implicit GEMM ----------------
// y[m, o] = sum_{k, c} sample(x; m, k, c) * Wr[k*256+c, o]
// block: BM=128 pixels x BN=256 outputs, 512 threads, 8x8 microtile (f32x2 packed).
__global__ __launch_bounds__(NTHR, 1) void dcn_gemm_kernel(const float* __restrict__ X)
{
    __shared__ __align__(16) float As[BK][BM];    // 8 KB
    __shared__ __align__(16) float Bs[BK][BN];    // 16 KB
    __shared__ int2   tI[BM][9];                  // 9 KB
    __shared__ float2 tF[BM][9];                  // 9 KB

    int tid  = threadIdx.x;
    int m0   = blockIdx.x * BM;
    int n    = m0 / HW;
    int pix0 = m0 - n * HW;

    // ---- build per-(pixel,k) sampling table ----
    for (int e = tid; e < BM * 9; e += NTHR) {
        int mi = e / 9, k = e - mi * 9;
        int pix = pix0 + mi;
        int h = pix / WW, w = pix - h * WW;
        float dy = g_off[((n * 18 + 2 * k) * HH + h) * WW + w];
        float dx = g_off[((n * 18 + 2 * k + 1) * HH + h) * WW + w];
        float py = (float)(h + k / 3 - 1) + dy;
        float px = (float)(w + (k % 3) - 1) + dx;
        float fy = floorf(py), fx = floorf(px);
        tI[mi][k] = make_int2((int)fy, (int)fx);
        tF[mi][k] = make_float2(py - fy, px - fx);
    }
    __syncthreads();

    unsigned long long acc[4][8];
#pragma unroll
    for (int a = 0; a < 4; a++)
#pragma unroll
        for (int b = 0; b < 8; b++) acc[a][b] = 0ull;

    int tm = tid & 15;          // 16 groups along M (8 rows each)
    int tn = tid >> 4;          // 32 groups along N (8 cols each)
    int mA  = tid & 127;        // A-fill pixel
    int clA = tid >> 7;         // A-fill c-sub 0..3
    const float* xn = X + (size_t)(n * CC) * HW;

    for (int k = 0; k < 9; k++) {
        // bilinear geometry for (mA, k): constant across the 16 c-chunks
        int2   ii = tI[mA][k];
        float2 ff = tF[mA][k];
        int y0 = ii.x, x0 = ii.y;
        float wy = ff.x, wx = ff.y;
        float w00 = (1.f - wy) * (1.f - wx);
        float w01 = (1.f - wy) * wx;
        float w10 = wy * (1.f - wx);
        float w11 = wy * wx;
        bool vy0 = (unsigned)y0       < (unsigned)HH;
        bool vy1 = (unsigned)(y0 + 1) < (unsigned)HH;
        bool vx0 = (unsigned)x0       < (unsigned)WW;
        bool vx1 = (unsigned)(x0 + 1) < (unsigned)WW;
        int yc0 = min(max(y0, 0), HH - 1), yc1 = min(max(y0 + 1, 0), HH - 1);
        int xc0 = min(max(x0, 0), WW - 1), xc1 = min(max(x0 + 1, 0), WW - 1);
        int i00 = yc0 * WW + xc0, i01 = yc0 * WW + xc1;
        int i10 = yc1 * WW + xc0, i11 = yc1 * WW + xc1;
        bool p00 = vy0 && vx0, p01 = vy0 && vx1, p10 = vy1 && vx0, p11 = vy1 && vx1;

        for (int sub = 0; sub < 16; sub++) {
            int c0 = sub << 4;
            // ---- fill B tile (16 x 256), coalesced ----
#pragma unroll
            for (int i = 0; i < 8; i++) {
                int e = tid + i * NTHR;
                int r = e >> 8, col = e & 255;
                Bs[r][col] = g_Wr[(k * 256 + c0 + r) * 256 + col];
            }
            // ---- fill A tile (16 x 128) via bilinear gather ----
            {
                const float* xb = xn + (size_t)(c0 + clA) * HW;
#pragma unroll
                for (int i = 0; i < 4; i++) {
                    float v00 = p00 ? xb[i00] : 0.f;
                    float v01 = p01 ? xb[i01] : 0.f;
                    float v10 = p10 ? xb[i10] : 0.f;
                    float v11 = p11 ? xb[i11] : 0.f;
                    As[clA + 4 * i][mA] =
                        fmaf(w00, v00, fmaf(w01, v01, fmaf(w10, v10, w11 * v11)));
                    xb += 4 * HW;
                }
            }
            __syncthreads();

            // ---- 8x8 microtile, f32x2-packed outer products ----
#pragma unroll
            for (int ccs = 0; ccs < BK; ccs++) {
                ulonglong2 aA = *(const ulonglong2*)&As[ccs][tm * 8];
                ulonglong2 aB = *(const ulonglong2*)&As[ccs][tm * 8 + 4];
                float4 b0 = *(const float4*)&Bs[ccs][tn * 8];
                float4 b1 = *(const float4*)&Bs[ccs][tn * 8 + 4];
                unsigned long long ap0 = aA.x, ap1 = aA.y, ap2 = aB.x, ap3 = aB.y;
                float bf[8] = {b0.x, b0.y, b0.z, b0.w, b1.x, b1.y, b1.z, b1.w};
#pragma unroll
                for (int j = 0; j < 8; j++) {
                    unsigned long long bb = pack2(bf[j], bf[j]);
                    ffma2(acc[0][j], ap0, bb);
                    ffma2(acc[1][j], ap1, bb);
                    ffma2(acc[2][j], ap2, bb);
                    ffma2(acc[3][j], ap3, bb);
                }
            }
            __syncthreads();
        }
    }

    // ---- epilogue: store y, accumulate BN stats ----
    float ls[8], lq[8];
#pragma unroll
    for (int j = 0; j < 8; j++) {
        float v[8];
#pragma unroll
        for (int mp = 0; mp < 4; mp++) unpack2(acc[mp][j], v[2 * mp], v[2 * mp + 1]);
        float s = 0.f, q = 0.f;
#pragma unroll
        for (int r = 0; r < 8; r++) { s += v[r]; q = fmaf(v[r], v[r], q); }
        ls[j] = s; lq[j] = q;
        int o = tn * 8 + j;
        float* yp = g_y + (size_t)(n * OO + o) * HW + pix0 + tm * 8;
        *(float4*)(yp)     = make_float4(v[0], v[1], v[2], v[3]);
        *(float4*)(yp + 4) = make_float4(v[4], v[5], v[6], v[7]);
    }
    // reduce across the 16 tm-lanes sharing the same o-set
#pragma unroll
    for (int j = 0; j < 8; j++) {
#pragma unroll
        for (int d = 8; d >= 1; d >>= 1) {
            ls[j] += __shfl_xor_sync(0xFFFFFFFFu, ls[j], d);
            lq[j] += __shfl_xor_sync(0xFFFFFFFFu, lq[j], d);
        }
    }
    if ((tid & 15) == 0) {
#pragma unroll
        for (int j = 0; j < 8; j++) {
            atomicAdd(&g_sum[tn * 8 + j], ls[j]);
            atomicAdd(&g_sq[tn * 8 + j],  lq[j]);
        }
    }
}

// ---------------- kernel 5: finalize BN stats ----------------
__global__ void finalize_kernel(const float* __restrict__ gamma,
                                const float* __restrict__ beta) {
    int o = threadIdx.x;
    const float inv_n = 1.f / (float)NHW;
    float m = g_sum[o] * inv_n;
    float v = g_sq[o] * inv_n - m * m;
    float a = v + 1e-5f;
    float is = rsqrtf(a);
    is = is * (1.5f - 0.5f * a * is * is);   // one Newton step
    float sc = is * gamma[o];
    g_scale[o] = sc;
    g_shift[o] = beta[o] - m * sc;
}

// ---------------- kernel 6: normalize + relu ----------------
__global__ void bn_relu_kernel(float* __restrict__ out) {
    int i = blockIdx.x * blockDim.x + threadIdx.x;
    int stride = gridDim.x * blockDim.x;
    const float4* y4 = (const float4*)g_y;
    float4* o4 = (float4*)out;
    const int total4 = NN * OO * HW / 4;       // 2359296
    for (; i < total4; i += stride) {
        int o = (i / (HW / 4)) & 255;
        float sc = g_scale[o], sh = g_shift[o];
        float4 v = y4[i];
        v.x = fmaxf(fmaf(v.x, sc, sh), 0.f);
        v.y = fmaxf(fmaf(v.y, sc, sh), 0.f);
        v.z = fmaxf(fmaf(v.z, sc, sh), 0.f);
        v.w = fmaxf(fmaf(v.w, sc, sh), 0.f);
        o4[i] = v;
    }
}

// ---------------- launch ----------------
extern "C" void kernel_launch(void* const* d_in, const int* in_sizes, int n_in,
                              void* d_out, int out_size) {
    const float* x     = (const float*)d_in[0];
    const float* w_off = (const float*)d_in[1];
    const float* b_off = (const float*)d_in[2];
    const float* w_dcn = (const float*)d_in[3];
    const float* gamma = (const float*)d_in[4];
    const float* beta  = (const float*)d_in[5];

    zero_stats_kernel<<<1, 256>>>();
    reorder_w_kernel<<<1152, 512>>>(w_dcn);                 // 589824 elems exact
    offset_conv_kernel<<<dim3(6, 6, NN), 256>>>(x, w_off, b_off);
    dcn_gemm_kernel<<<NHW / BM, NTHR>>>(x);                 // 288 blocks
    finalize_kernel<<<1, 256>>>(gamma, beta);
    bn_relu_kernel<<<2304, 256>>>((float*)d_out);
}

// round 8
// speedup vs baseline: 1.5533x; 1.5516x over previous
#include <cuda_runtime.h>
#include <cuda_bf16.h>
#include <cstdint>

#define NN   4
#define CC   256
#define OO   256
#define HH   96
#define WW   96
#define HW   9216
#define NHW  36864

#define BM   128
#define BN   256
#define BK   32
#define NTHR 512
#define NCHUNK 72           // 2304 / 32

// GEMM smem layout (bytes); A/B tiles use 80B row pitch (40 bf16) so that
// fragment lds banks (g*20 + c) mod 32 are all-distinct -> conflict-free.
#define SM_WT   0                      // float4 [9][128]  = 18432
#define SM_IT   18432                  // ushort4[9][128]  =  9216
#define SM_AH   27648                  // 128 rows * 80B   = 10240
#define SM_AL   37888
#define SM_BH   48128                  // 256 rows * 80B   = 20480
#define SM_BL   68608
#define SMEM_GEMM 89088

// ---- scratch globals (no allocation allowed) ----
__device__ __align__(256) float         g_off[NN * 18 * HW];
__device__ __align__(256) __nv_bfloat16 g_Bh[OO * 2304];
__device__ __align__(256) __nv_bfloat16 g_Bl[OO * 2304];
__device__ __align__(256) float2        g_wo2[CC * 81];
__device__ __align__(256) float         g_y[NHW * 256];   // pixel-major [gpix][o]
__device__ float g_sum[OO];
__device__ float g_sq[OO];
__device__ float g_scale[OO];
__device__ float g_shift[OO];

// ---- helpers ----
__device__ __forceinline__ uint32_t pkbf(__nv_bfloat16 a, __nv_bfloat16 b) {
    return (uint32_t)__bfloat16_as_ushort(a) | ((uint32_t)__bfloat16_as_ushort(b) << 16);
}
__device__ __forceinline__ unsigned long long pack2(float x, float y) {
    unsigned long long r;
    asm("mov.b64 %0, {%1, %2};" : "=l"(r) : "f"(x), "f"(y));
    return r;
}
__device__ __forceinline__ void unpack2(unsigned long long v, float &x, float &y) {
    asm("mov.b64 {%0, %1}, %2;" : "=f"(x), "=f"(y) : "l"(v));
}
__device__ __forceinline__ void ffma2(unsigned long long &d, unsigned long long a,
                                      unsigned long long b) {
    asm("fma.rn.f32x2 %0, %1, %2, %0;" : "+l"(d) : "l"(a), "l"(b));
}
__device__ __forceinline__ void mma_bf16(float* d, const uint32_t* a,
                                         uint32_t b0, uint32_t b1) {
    asm volatile(
        "mma.sync.aligned.m16n8k16.row.col.f32.bf16.bf16.f32 "
        "{%0,%1,%2,%3}, {%4,%5,%6,%7}, {%8,%9}, {%0,%1,%2,%3};"
        : "+f"(d[0]), "+f"(d[1]), "+f"(d[2]), "+f"(d[3])
        : "r"(a[0]), "r"(a[1]), "r"(a[2]), "r"(a[3]), "r"(b0), "r"(b1));
}

// ---------------- kernel 1: weight prep ----------------
__global__ void prep_kernel(const float* __restrict__ w_dcn,
                            const float* __restrict__ w_off) {
    int e = blockIdx.x * blockDim.x + threadIdx.x;   // 589824 exact
    {
        int o = e / 2304, r = e - o * 2304;
        int kt = r >> 8, c = r & 255;
        float v = w_dcn[(o * CC + c) * 9 + kt];
        __nv_bfloat16 hi = __float2bfloat16(v);
        g_Bh[e] = hi;
        g_Bl[e] = __float2bfloat16(v - __bfloat162float(hi));
    }
    if (e < CC * 81) {
        int c = e / 81, r = e - c * 81;
        int t = r / 9, p = r - t * 9;
        g_wo2[e] = make_float2(w_off[(2 * p) * 2304 + c * 9 + t],
                               w_off[(2 * p + 1) * 2304 + c * 9 + t]);
    }
}

// ---------------- kernel 2: offset conv (3x3, 256->18), f32x2 ----------------
__global__ __launch_bounds__(256) void offset_conv_kernel(
    const float* __restrict__ x, const float* __restrict__ b_off)
{
    __shared__ float xs[4][18][19];
    __shared__ unsigned long long ws[4][81];
    int n  = blockIdx.z;
    int h0 = blockIdx.y * 16, w0 = blockIdx.x * 16;
    int tid = threadIdx.x;
    int ty = tid >> 4, tx = tid & 15;

    unsigned long long acc[9];
#pragma unroll
    for (int p = 0; p < 9; p++) acc[p] = 0ull;
    const unsigned long long* wo2 = (const unsigned long long*)g_wo2;

    for (int cg = 0; cg < 64; cg++) {
        int cb = cg * 4;
        for (int i = tid; i < 1296; i += 256) {
            int cl = i / 324, r2 = i - cl * 324;
            int r = r2 / 18, q = r2 - r * 18;
            int hh = h0 - 1 + r, wp = w0 - 1 + q;
            float v = 0.f;
            if ((unsigned)hh < (unsigned)HH && (unsigned)wp < (unsigned)WW)
                v = x[((n * CC + cb + cl) * HH + hh) * WW + wp];
            xs[cl][r][q] = v;
        }
        for (int i = tid; i < 324; i += 256) {
            int cl = i / 81, r = i - cl * 81;
            ws[cl][r] = wo2[(cb + cl) * 81 + r];
        }
        __syncthreads();
#pragma unroll
        for (int cl = 0; cl < 4; cl++) {
            float xv[9];
#pragma unroll
            for (int t = 0; t < 9; t++) xv[t] = xs[cl][ty + t / 3][tx + t % 3];
#pragma unroll
            for (int t = 0; t < 9; t++) {
                unsigned long long bb = pack2(xv[t], xv[t]);
#pragma unroll
                for (int p = 0; p < 9; p++) ffma2(acc[p], ws[cl][t * 9 + p], bb);
            }
        }
        __syncthreads();
    }
    int h = h0 + ty, w = w0 + tx;
#pragma unroll
    for (int p = 0; p < 9; p++) {
        float a0, a1;
        unpack2(acc[p], a0, a1);
        g_off[((n * 18 + 2 * p) * HH + h) * WW + w]     = a0 + b_off[2 * p];
        g_off[((n * 18 + 2 * p + 1) * HH + h) * WW + w] = a1 + b_off[2 * p + 1];
    }
}

// ---------------- kernel 3: zero BN accumulators ----------------
__global__ void zero_stats_kernel() {
    g_sum[threadIdx.x] = 0.f;
    g_sq[threadIdx.x]  = 0.f;
}

// ---------------- kernel 4: HMMA fused deformable-gather GEMM ----------------
// y[gpix][o] = sum_{kt,c} bilinear(x; gpix, kt, c) * w[o][kt*256+c]
// 3-term bf16 compensation: AhBh + AhBl + AlBh. 16 warps, warp tile 32x64.
__global__ __launch_bounds__(NTHR, 1) void dcn_gemm_kernel(const float* __restrict__ X)
{
    extern __shared__ __align__(128) char smem[];
    float4*  wt = (float4*)(smem + SM_WT);
    ushort4* it = (ushort4*)(smem + SM_IT);

    int tid = threadIdx.x;
    int wid = tid >> 5, lid = tid & 31;
    int m0   = blockIdx.x * BM;
    int n    = m0 / HW;
    int pix0 = m0 - n * HW;

    // ---- bilinear tables: [tap][pixel] clamped u16 indices + masked weights ----
    for (int e = tid; e < BM * 9; e += NTHR) {
        int k = e / BM, mi = e - k * BM;
        int pix = pix0 + mi;
        int h = pix / WW, w = pix - h * WW;
        float dy = g_off[((n * 18 + 2 * k) * HH + h) * WW + w];
        float dx = g_off[((n * 18 + 2 * k + 1) * HH + h) * WW + w];
        float py = (float)(h + k / 3 - 1) + dy;
        float px = (float)(w + (k % 3) - 1) + dx;
        float fy = floorf(py), fx = floorf(px);
        int y0 = (int)fy, x0 = (int)fx;
        float wy = py - fy, wx = px - fx;
        float m00 = ((unsigned)y0 < HH && (unsigned)x0 < WW) ? 1.f : 0.f;
        float m01 = ((unsigned)y0 < HH && (unsigned)(x0 + 1) < WW) ? 1.f : 0.f;
        float m10 = ((unsigned)(y0 + 1) < HH && (unsigned)x0 < WW) ? 1.f : 0.f;
        float m11 = ((unsigned)(y0 + 1) < HH && (unsigned)(x0 + 1) < WW) ? 1.f : 0.f;
        int yc0 = min(max(y0, 0), HH - 1), yc1 = min(max(y0 + 1, 0), HH - 1);
        int xc0 = min(max(x0, 0), WW - 1), xc1 = min(max(x0 + 1, 0), WW - 1);
        wt[e] = make_float4((1.f - wy) * (1.f - wx) * m00, (1.f - wy) * wx * m01,
                            wy * (1.f - wx) * m10, wy * wx * m11);
        it[e] = make_ushort4((unsigned short)(yc0 * WW + xc0), (unsigned short)(yc0 * WW + xc1),
                             (unsigned short)(yc1 * WW + xc0), (unsigned short)(yc1 * WW + xc1));
    }

    float acc[2][8][4];
#pragma unroll
    for (int a = 0; a < 2; a++)
#pragma unroll
        for (int b = 0; b < 8; b++)
#pragma unroll
            for (int c = 0; c < 4; c++) acc[a][b][c] = 0.f;

    int wm = wid & 3, wn = wid >> 2;          // warp grid 4 (M) x 4 (N)
    int g  = lid >> 2, c4 = lid & 3;          // fragment lane coords
    int bRow = tid >> 1, bHalf = tid & 1;     // B-fill role
    int aCh  = wid * 2;                       // A-fill channel pair
    const float* xn = X + (size_t)n * CC * HW;

    for (int ch = 0; ch < NCHUNK; ch++) {
        int kt = ch >> 3, c0 = (ch & 7) << 5;
        __syncthreads();   // prior MMA done reading tiles

        // ---- B tiles: 256 rows x 32 bf16 (hi & lo) ----
        {
            const __nv_bfloat16* sh = g_Bh + (size_t)bRow * 2304 + kt * 256 + c0 + bHalf * 16;
            const __nv_bfloat16* sl = g_Bl + (size_t)bRow * 2304 + kt * 256 + c0 + bHalf * 16;
            uint4 h0 = ((const uint4*)sh)[0], h1 = ((const uint4*)sh)[1];
            uint4 l0 = ((const uint4*)sl)[0], l1 = ((const uint4*)sl)[1];
            char* bh = smem + SM_BH + bRow * 80 + bHalf * 32;
            char* bl = smem + SM_BL + bRow * 80 + bHalf * 32;
            *(uint4*)(bh) = h0; *(uint4*)(bh + 16) = h1;
            *(uint4*)(bl) = l0; *(uint4*)(bl + 16) = l1;
        }
        // ---- A tiles: 128 pixels x 32 channels, bilinear gather, hi/lo split ----
        {
            const float* xb0 = xn + (size_t)(c0 + aCh) * HW;
#pragma unroll
            for (int rg = 0; rg < 4; rg++) {
                int mi = (rg << 5) + lid;
                float4  w4 = wt[kt * BM + mi];
                ushort4 i4 = it[kt * BM + mi];
                int j0 = i4.x, j1 = i4.y, j2 = i4.z, j3 = i4.w;
                float v0 = w4.x * xb0[j0] + w4.y * xb0[j1] + w4.z * xb0[j2] + w4.w * xb0[j3];
                const float* xb1 = xb0 + HW;
                float v1 = w4.x * xb1[j0] + w4.y * xb1[j1] + w4.z * xb1[j2] + w4.w * xb1[j3];
                __nv_bfloat16 h0 = __float2bfloat16(v0);
                __nv_bfloat16 h1 = __float2bfloat16(v1);
                uint32_t off = mi * 80 + aCh * 2;
                *(uint32_t*)(smem + SM_AH + off) = pkbf(h0, h1);
                *(uint32_t*)(smem + SM_AL + off) =
                    pkbf(__float2bfloat16(v0 - __bfloat162float(h0)),
                         __float2bfloat16(v1 - __bfloat162float(h1)));
            }
        }
        __syncthreads();

        // ---- MMA: 3 terms x 2 k-steps x (2 m-tiles x 8 n-tiles) ----
#pragma unroll
        for (int t = 0; t < 3; t++) {
            const char* Ab = smem + (t == 2 ? SM_AL : SM_AH);
            const char* Bb = smem + (t == 1 ? SM_BL : SM_BH);
#pragma unroll
            for (int ks = 0; ks < 2; ks++) {
                int cb = c4 * 4 + ks * 32;
                uint32_t a0[4], a1[4];
                const char* A0 = Ab + (wm * 32 + g) * 80 + cb;
                a0[0] = *(const uint32_t*)(A0);
                a0[1] = *(const uint32_t*)(A0 + 8 * 80);
                a0[2] = *(const uint32_t*)(A0 + 16);
                a0[3] = *(const uint32_t*)(A0 + 8 * 80 + 16);
                const char* A1 = A0 + 16 * 80;
                a1[0] = *(const uint32_t*)(A1);
                a1[1] = *(const uint32_t*)(A1 + 8 * 80);
                a1[2] = *(const uint32_t*)(A1 + 16);
                a1[3] = *(const uint32_t*)(A1 + 8 * 80 + 16);
#pragma unroll
                for (int nt = 0; nt < 8; nt++) {
                    const char* B0 = Bb + (wn * 64 + nt * 8 + g) * 80 + cb;
                    uint32_t b0 = *(const uint32_t*)(B0);
                    uint32_t b1 = *(const uint32_t*)(B0 + 16);
                    mma_bf16(acc[0][nt], a0, b0, b1);
                    mma_bf16(acc[1][nt], a1, b0, b1);
                }
            }
        }
    }

    // ---- epilogue: D frags -> g_y[gpix][o] (float2, sector-aligned) ----
    float* yb = g_y + (size_t)m0 * 256;
#pragma unroll
    for (int mt = 0; mt < 2; mt++) {
        int pr = wm * 32 + mt * 16 + g;
#pragma unroll
        for (int nt = 0; nt < 8; nt++) {
            int oc = wn * 64 + nt * 8 + c4 * 2;
            *(float2*)(yb + (size_t)pr * 256 + oc) =
                make_float2(acc[mt][nt][0], acc[mt][nt][1]);
            *(float2*)(yb + (size_t)(pr + 8) * 256 + oc) =
                make_float2(acc[mt][nt][2], acc[mt][nt][3]);
        }
    }
}

// ---------------- kernel 5: BN partial stats (coalesced rows + atomics) ------
__global__ __launch_bounds__(256) void stats_kernel() {
    int o = threadIdx.x;
    int base = blockIdx.x * 128;
    float s = 0.f, q = 0.f;
    const float* p = g_y + (size_t)base * 256 + o;
    for (int i = 0; i < 128; i++) {
        float v = p[(size_t)i * 256];
        s += v;
        q = fmaf(v, v, q);
    }
    atomicAdd(&g_sum[o], s);
    atomicAdd(&g_sq[o], q);
}

// ---------------- kernel 6: finalize scale/shift ----------------
__global__ void finalize_kernel(const float* __restrict__ gamma,
                                const float* __restrict__ beta) {
    int o = threadIdx.x;
    const float inv_n = 1.f / (float)NHW;
    float m = g_sum[o] * inv_n;
    float v = g_sq[o] * inv_n - m * m;
    float a = v + 1e-5f;
    float is = rsqrtf(a);
    is = is * (1.5f - 0.5f * a * is * is);   // Newton step
    float sc = is * gamma[o];
    g_scale[o] = sc;
    g_shift[o] = beta[o] - m * sc;
}

// ---------------- kernel 7: BN + ReLU + transpose to NCHW ----------------
__global__ __launch_bounds__(256) void bn_relu_kernel(float* __restrict__ out) {
    __shared__ float t[32][33];
    int gp0 = blockIdx.x * 32;               // global pixel tile (never crosses n)
    int o0  = blockIdx.y * 32;
    int tx = threadIdx.x & 31, ty = threadIdx.x >> 5;
    int n  = gp0 / HW;
    int lp0 = gp0 - n * HW;
#pragma unroll
    for (int j = 0; j < 4; j++) {
        int pr = ty + j * 8;
        t[pr][tx] = g_y[(size_t)(gp0 + pr) * 256 + o0 + tx];
    }
    __syncthreads();
#pragma unroll
    for (int j = 0; j < 4; j++) {
        int oo = o0 + ty + j * 8;
        float v = t[tx][ty + j * 8];
        v = fmaxf(fmaf(v, g_scale[oo], g_shift[oo]), 0.f);
        out[((size_t)(n * 256 + oo)) * HW + lp0 + tx] = v;
    }
}

// ---------------- launch ----------------
extern "C" void kernel_launch(void* const* d_in, const int* in_sizes, int n_in,
                              void* d_out, int out_size) {
    const float* x     = (const float*)d_in[0];
    const float* w_off = (const float*)d_in[1];
    const float* b_off = (const float*)d_in[2];
    const float* w_dcn = (const float*)d_in[3];
    const float* gamma = (const float*)d_in[4];
    const float* beta  = (const float*)d_in[5];

    cudaFuncSetAttribute(dcn_gemm_kernel,
                         cudaFuncAttributeMaxDynamicSharedMemorySize, SMEM_GEMM);

    prep_kernel<<<1152, 512>>>(w_dcn, w_off);
    offset_conv_kernel<<<dim3(6, 6, NN), 256>>>(x, b_off);
    zero_stats_kernel<<<1, 256>>>();
    dcn_gemm_kernel<<<NHW / BM, NTHR, SMEM_GEMM>>>(x);     // 288 CTAs
    stats_kernel<<<288, 256>>>();
    finalize_kernel<<<1, 256>>>(gamma, beta);
    bn_relu_kernel<<<dim3(NHW / 32, 8), 256>>>((float*)d_out);
}

// round 9
// speedup vs baseline: 2.0640x; 1.3288x over previous
#include <cuda_runtime.h>
#include <cuda_bf16.h>
#include <cstdint>

#define NN   4
#define CC   256
#define OO   256
#define HH   96
#define WW   96
#define HW   9216
#define NHW  36864

#define BM   128
#define NTHR 512
#define NCHUNK 72           // 2304 / 32

// GEMM smem (bytes). Tiles use 80B row pitch (40 bf16): fragment lds banks
// (g*20+c) mod 32 all-distinct -> conflict-free. Two pipeline stages.
#define SM_WT    0                      // float4 [9][128]  = 18432
#define SM_IT    18432                  // ushort4[9][128]  =  9216
#define SM_ST0   27648
#define STAGE_SZ 61440                  // AH 10240 | AL 10240 | BH 20480 | BL 20480
#define O_AH 0
#define O_AL 10240
#define O_BH 20480
#define O_BL 40960
#define SMEM_GEMM (SM_ST0 + 2*STAGE_SZ) // 150528

// ---- scratch globals ----
__device__ __align__(256) float         g_off[NN * 18 * HW];
__device__ __align__(256) __nv_bfloat16 g_Bh[OO * 2304];
__device__ __align__(256) __nv_bfloat16 g_Bl[OO * 2304];
__device__ __align__(256) float2        g_wo2[CC * 81];
__device__ __align__(256) float         g_y[NHW * 256];   // pixel-major [gpix][o]
__device__ float g_sum[OO];
__device__ float g_sq[OO];
__device__ float g_scale[OO];
__device__ float g_shift[OO];

// ---- helpers ----
__device__ __forceinline__ uint32_t smem_addr(const void* p) {
    uint32_t a;
    asm("{ .reg .u64 t; cvta.to.shared.u64 t, %1; cvt.u32.u64 %0, t; }" : "=r"(a) : "l"(p));
    return a;
}
__device__ __forceinline__ void cpa16(uint32_t d, const void* s) {
    asm volatile("cp.async.cg.shared.global [%0], [%1], 16;" :: "r"(d), "l"(s) : "memory");
}
__device__ __forceinline__ void cpa8(uint32_t d, const void* s) {
    asm volatile("cp.async.ca.shared.global [%0], [%1], 8;" :: "r"(d), "l"(s) : "memory");
}
__device__ __forceinline__ void cpa4z(uint32_t d, const void* s, int sz) {
    asm volatile("cp.async.ca.shared.global [%0], [%1], 4, %2;" :: "r"(d), "l"(s), "r"(sz) : "memory");
}
__device__ __forceinline__ void cpa_commit() {
    asm volatile("cp.async.commit_group;" ::: "memory");
}
__device__ __forceinline__ void cpa_wait0() {
    asm volatile("cp.async.wait_group 0;" ::: "memory");
}
__device__ __forceinline__ uint32_t pkbf(__nv_bfloat16 a, __nv_bfloat16 b) {
    return (uint32_t)__bfloat16_as_ushort(a) | ((uint32_t)__bfloat16_as_ushort(b) << 16);
}
__device__ __forceinline__ unsigned long long pack2(float x, float y) {
    unsigned long long r;
    asm("mov.b64 %0, {%1, %2};" : "=l"(r) : "f"(x), "f"(y));
    return r;
}
__device__ __forceinline__ void unpack2(unsigned long long v, float &x, float &y) {
    asm("mov.b64 {%0, %1}, %2;" : "=f"(x), "=f"(y) : "l"(v));
}
__device__ __forceinline__ void ffma2(unsigned long long &d, unsigned long long a,
                                      unsigned long long b) {
    asm("fma.rn.f32x2 %0, %1, %2, %0;" : "+l"(d) : "l"(a), "l"(b));
}
__device__ __forceinline__ void mma_bf16(float* d, const uint32_t* a,
                                         uint32_t b0, uint32_t b1) {
    asm volatile(
        "mma.sync.aligned.m16n8k16.row.col.f32.bf16.bf16.f32 "
        "{%0,%1,%2,%3}, {%4,%5,%6,%7}, {%8,%9}, {%0,%1,%2,%3};"
        : "+f"(d[0]), "+f"(d[1]), "+f"(d[2]), "+f"(d[3])
        : "r"(a[0]), "r"(a[1]), "r"(a[2]), "r"(a[3]), "r"(b0), "r"(b1));
}

// ---------------- kernel 1: weight prep ----------------
__global__ void prep_kernel(const float* __restrict__ w_dcn,
                            const float* __restrict__ w_off) {
    int e = blockIdx.x * blockDim.x + threadIdx.x;   // 589824 exact
    {
        int o = e / 2304, r = e - o * 2304;
        int kt = r >> 8, c = r & 255;
        float v = w_dcn[(o * CC + c) * 9 + kt];
        __nv_bfloat16 hi = __float2bfloat16(v);
        g_Bh[e] = hi;
        g_Bl[e] = __float2bfloat16(v - __bfloat162float(hi));
    }
    if (e < CC * 81) {
        int c = e / 81, r = e - c * 81;
        int t = r / 9, p = r - t * 9;
        g_wo2[e] = make_float2(w_off[(2 * p) * 2304 + c * 9 + t],
                               w_off[(2 * p + 1) * 2304 + c * 9 + t]);
    }
}

// ---------------- kernel 2: offset conv, cp.async double-buffered ----------------
__global__ __launch_bounds__(256) void offset_conv_kernel(
    const float* __restrict__ x, const float* __restrict__ b_off)
{
    __shared__ float xs[2][4][18][19];
    __shared__ unsigned long long ws[2][4][81];
    int n  = blockIdx.z;
    int h0 = blockIdx.y * 16, w0 = blockIdx.x * 16;
    int tid = threadIdx.x;
    int ty = tid >> 4, tx = tid & 15;
    uint32_t xs_b = smem_addr(&xs[0][0][0][0]);
    uint32_t ws_b = smem_addr(&ws[0][0][0]);
    const unsigned long long* wo2 = (const unsigned long long*)g_wo2;

    unsigned long long acc[9];
#pragma unroll
    for (int p = 0; p < 9; p++) acc[p] = 0ull;

    auto prefetch = [&](int cg, int st) {
        int cb = cg * 4;
        for (int i = tid; i < 1296; i += 256) {
            int cl = i / 324, r2 = i - cl * 324;
            int r = r2 / 18, q = r2 - r * 18;
            int hh = h0 - 1 + r, wp = w0 - 1 + q;
            int ok = ((unsigned)hh < (unsigned)HH && (unsigned)wp < (unsigned)WW) ? 4 : 0;
            int hc = min(max(hh, 0), HH - 1), wc = min(max(wp, 0), WW - 1);
            cpa4z(xs_b + (uint32_t)(((st * 4 + cl) * 342) + r * 19 + q) * 4,
                  &x[((n * CC + cb + cl) * HH + hc) * WW + wc], ok);
        }
        for (int i = tid; i < 324; i += 256) {
            int cl = i / 81, r = i - cl * 81;
            cpa8(ws_b + (uint32_t)((st * 4 + cl) * 81 + r) * 8, &wo2[(cb + cl) * 81 + r]);
        }
        cpa_commit();
    };

    prefetch(0, 0);
    cpa_wait0();
    __syncthreads();

    for (int cg = 0; cg < 64; cg++) {
        int st = cg & 1;
        if (cg < 63) prefetch(cg + 1, st ^ 1);
#pragma unroll
        for (int cl = 0; cl < 4; cl++) {
            float xv[9];
#pragma unroll
            for (int t = 0; t < 9; t++) xv[t] = xs[st][cl][ty + t / 3][tx + t % 3];
#pragma unroll
            for (int t = 0; t < 9; t++) {
                unsigned long long bb = pack2(xv[t], xv[t]);
#pragma unroll
                for (int p = 0; p < 9; p++) ffma2(acc[p], ws[st][cl][t * 9 + p], bb);
            }
        }
        cpa_wait0();
        __syncthreads();
    }
    int h = h0 + ty, w = w0 + tx;
#pragma unroll
    for (int p = 0; p < 9; p++) {
        float a0, a1;
        unpack2(acc[p], a0, a1);
        g_off[((n * 18 + 2 * p) * HH + h) * WW + w]     = a0 + b_off[2 * p];
        g_off[((n * 18 + 2 * p + 1) * HH + h) * WW + w] = a1 + b_off[2 * p + 1];
    }
}

// ---------------- kernel 3: zero BN accumulators ----------------
__global__ void zero_stats_kernel() {
    g_sum[threadIdx.x] = 0.f;
    g_sq[threadIdx.x]  = 0.f;
}

// ---------------- kernel 4: HMMA GEMM, 2-stage software pipeline ----------------
__global__ __launch_bounds__(NTHR, 1) void dcn_gemm_kernel(const float* __restrict__ X)
{
    extern __shared__ __align__(128) char smem[];
    float4*  wt = (float4*)(smem + SM_WT);
    ushort4* it = (ushort4*)(smem + SM_IT);
    uint32_t sb = smem_addr(smem);

    int tid = threadIdx.x;
    int wid = tid >> 5, lid = tid & 31;
    int m0   = blockIdx.x * BM;
    int n    = m0 / HW;
    int pix0 = m0 - n * HW;

    // ---- bilinear tables ----
    for (int e = tid; e < BM * 9; e += NTHR) {
        int k = e / BM, mi = e - k * BM;
        int pix = pix0 + mi;
        int h = pix / WW, w = pix - h * WW;
        float dy = g_off[((n * 18 + 2 * k) * HH + h) * WW + w];
        float dx = g_off[((n * 18 + 2 * k + 1) * HH + h) * WW + w];
        float py = (float)(h + k / 3 - 1) + dy;
        float px = (float)(w + (k % 3) - 1) + dx;
        float fy = floorf(py), fx = floorf(px);
        int y0 = (int)fy, x0 = (int)fx;
        float wy = py - fy, wx = px - fx;
        float m00 = ((unsigned)y0 < HH && (unsigned)x0 < WW) ? 1.f : 0.f;
        float m01 = ((unsigned)y0 < HH && (unsigned)(x0 + 1) < WW) ? 1.f : 0.f;
        float m10 = ((unsigned)(y0 + 1) < HH && (unsigned)x0 < WW) ? 1.f : 0.f;
        float m11 = ((unsigned)(y0 + 1) < HH && (unsigned)(x0 + 1) < WW) ? 1.f : 0.f;
        int yc0 = min(max(y0, 0), HH - 1), yc1 = min(max(y0 + 1, 0), HH - 1);
        int xc0 = min(max(x0, 0), WW - 1), xc1 = min(max(x0 + 1, 0), WW - 1);
        wt[e] = make_float4((1.f - wy) * (1.f - wx) * m00, (1.f - wy) * wx * m01,
                            wy * (1.f - wx) * m10, wy * wx * m11);
        it[e] = make_ushort4((unsigned short)(yc0 * WW + xc0), (unsigned short)(yc0 * WW + xc1),
                             (unsigned short)(yc1 * WW + xc0), (unsigned short)(yc1 * WW + xc1));
    }
    __syncthreads();

    float acc[2][8][4];
#pragma unroll
    for (int a = 0; a < 2; a++)
#pragma unroll
        for (int b = 0; b < 8; b++)
#pragma unroll
            for (int c = 0; c < 4; c++) acc[a][b][c] = 0.f;

    int wm = wid & 3, wn = wid >> 2;
    int g  = lid >> 2, c4 = lid & 3;
    int bRow = tid >> 1, bHalf = tid & 1;
    int aCh  = wid * 2;
    const float* xn = X + (size_t)n * CC * HW;

    // B cp.async for chunk (kt, c0) into stage base stN
    auto b_prefetch = [&](int kt, int c0, uint32_t stN) {
        const char* srcH = (const char*)(g_Bh + (size_t)bRow * 2304 + kt * 256 + c0 + bHalf * 16);
        const char* srcL = (const char*)(g_Bl + (size_t)bRow * 2304 + kt * 256 + c0 + bHalf * 16);
        uint32_t dH = sb + stN + O_BH + bRow * 80 + bHalf * 32;
        uint32_t dL = sb + stN + O_BL + bRow * 80 + bHalf * 32;
        cpa16(dH, srcH); cpa16(dH + 16, srcH + 16);
        cpa16(dL, srcL); cpa16(dL + 16, srcL + 16);
        cpa_commit();
    };
    // A dot+cvt+store for one row group
    auto a_store = [&](uint32_t stN, int mi, float4 w4, const float* va) {
        float v0 = w4.x * va[0] + w4.y * va[1] + w4.z * va[2] + w4.w * va[3];
        float v1 = w4.x * va[4] + w4.y * va[5] + w4.z * va[6] + w4.w * va[7];
        __nv_bfloat16 h0 = __float2bfloat16(v0);
        __nv_bfloat16 h1 = __float2bfloat16(v1);
        uint32_t off = mi * 80 + aCh * 2;
        *(uint32_t*)(smem + stN + O_AH + off) = pkbf(h0, h1);
        *(uint32_t*)(smem + stN + O_AL + off) =
            pkbf(__float2bfloat16(v0 - __bfloat162float(h0)),
                 __float2bfloat16(v1 - __bfloat162float(h1)));
    };
    // one MMA term over stage stS
    auto mma_term = [&](uint32_t stS, int AOFF, int BOFF) {
#pragma unroll
        for (int ks = 0; ks < 2; ks++) {
            int cb = c4 * 4 + ks * 32;
            uint32_t a0[4], a1[4];
            const char* A0 = smem + stS + AOFF + (wm * 32 + g) * 80 + cb;
            a0[0] = *(const uint32_t*)(A0);
            a0[1] = *(const uint32_t*)(A0 + 8 * 80);
            a0[2] = *(const uint32_t*)(A0 + 16);
            a0[3] = *(const uint32_t*)(A0 + 8 * 80 + 16);
            const char* A1 = A0 + 16 * 80;
            a1[0] = *(const uint32_t*)(A1);
            a1[1] = *(const uint32_t*)(A1 + 8 * 80);
            a1[2] = *(const uint32_t*)(A1 + 16);
            a1[3] = *(const uint32_t*)(A1 + 8 * 80 + 16);
#pragma unroll
            for (int nt = 0; nt < 8; nt++) {
                const char* B0 = smem + stS + BOFF + (wn * 64 + nt * 8 + g) * 80 + cb;
                uint32_t b0 = *(const uint32_t*)(B0);
                uint32_t b1 = *(const uint32_t*)(B0 + 16);
                mma_bf16(acc[0][nt], a0, b0, b1);
                mma_bf16(acc[1][nt], a1, b0, b1);
            }
        }
    };

    // ---- prologue: fill stage 0 with chunk 0 (kt=0, c0=0) ----
    b_prefetch(0, 0, SM_ST0);
    {
        const float* xb0 = xn + (size_t)aCh * HW;
#pragma unroll
        for (int rg = 0; rg < 4; rg++) {
            int mi = (rg << 5) + lid;
            float4  w4 = wt[mi];
            ushort4 i4 = it[mi];
            float va[8];
            va[0] = xb0[i4.x]; va[1] = xb0[i4.y]; va[2] = xb0[i4.z]; va[3] = xb0[i4.w];
            const float* xb1 = xb0 + HW;
            va[4] = xb1[i4.x]; va[5] = xb1[i4.y]; va[6] = xb1[i4.z]; va[7] = xb1[i4.w];
            a_store(SM_ST0, mi, w4, va);
        }
    }
    cpa_wait0();
    __syncthreads();

    // ---- main pipelined loop ----
    for (int ch = 0; ch < NCHUNK; ch++) {
        uint32_t stS = SM_ST0 + (uint32_t)(ch & 1) * STAGE_SZ;
        uint32_t stN = SM_ST0 + (uint32_t)((ch & 1) ^ 1) * STAGE_SZ;
        bool pf = (ch + 1 < NCHUNK);
        int kt2 = (ch + 1) >> 3, c02 = ((ch + 1) & 7) << 5;

        if (pf) b_prefetch(kt2, c02, stN);

        // A prefetch: rg 0,1 loads in flight during MMA term 0
        float va[16];
        float4 w40, w41;
        int mi0 = lid, mi1 = 32 + lid;
        const float* xb0 = xn + (size_t)(c02 + aCh) * HW;
        if (pf) {
            w40 = wt[kt2 * BM + mi0];
            ushort4 i40 = it[kt2 * BM + mi0];
            va[0] = xb0[i40.x]; va[1] = xb0[i40.y]; va[2] = xb0[i40.z]; va[3] = xb0[i40.w];
            const float* xb1 = xb0 + HW;
            va[4] = xb1[i40.x]; va[5] = xb1[i40.y]; va[6] = xb1[i40.z]; va[7] = xb1[i40.w];
            w41 = wt[kt2 * BM + mi1];
            ushort4 i41 = it[kt2 * BM + mi1];
            va[8]  = xb0[i41.x]; va[9]  = xb0[i41.y]; va[10] = xb0[i41.z]; va[11] = xb0[i41.w];
            va[12] = xb1[i41.x]; va[13] = xb1[i41.y]; va[14] = xb1[i41.z]; va[15] = xb1[i41.w];
        }

        mma_term(stS, O_AH, O_BH);

        if (pf) {
            a_store(stN, mi0, w40, va);
            a_store(stN, mi1, w41, va + 8);
            int mi2 = 64 + lid, mi3 = 96 + lid;
            w40 = wt[kt2 * BM + mi2];
            ushort4 i42 = it[kt2 * BM + mi2];
            va[0] = xb0[i42.x]; va[1] = xb0[i42.y]; va[2] = xb0[i42.z]; va[3] = xb0[i42.w];
            const float* xb1 = xb0 + HW;
            va[4] = xb1[i42.x]; va[5] = xb1[i42.y]; va[6] = xb1[i42.z]; va[7] = xb1[i42.w];
            w41 = wt[kt2 * BM + mi3];
            ushort4 i43 = it[kt2 * BM + mi3];
            va[8]  = xb0[i43.x]; va[9]  = xb0[i43.y]; va[10] = xb0[i43.z]; va[11] = xb0[i43.w];
            va[12] = xb1[i43.x]; va[13] = xb1[i43.y]; va[14] = xb1[i43.z]; va[15] = xb1[i43.w];
        }

        mma_term(stS, O_AH, O_BL);

        if (pf) {
            a_store(stN, 64 + lid, w40, va);
            a_store(stN, 96 + lid, w41, va + 8);
        }

        mma_term(stS, O_AL, O_BH);

        cpa_wait0();
        __syncthreads();
    }

    // ---- epilogue: D frags -> g_y[gpix][o] ----
    float* yb = g_y + (size_t)m0 * 256;
#pragma unroll
    for (int mt = 0; mt < 2; mt++) {
        int pr = wm * 32 + mt * 16 + g;
#pragma unroll
        for (int nt = 0; nt < 8; nt++) {
            int oc = wn * 64 + nt * 8 + c4 * 2;
            *(float2*)(yb + (size_t)pr * 256 + oc) =
                make_float2(acc[mt][nt][0], acc[mt][nt][1]);
            *(float2*)(yb + (size_t)(pr + 8) * 256 + oc) =
                make_float2(acc[mt][nt][2], acc[mt][nt][3]);
        }
    }
}

// ---------------- kernel 5: BN partial stats ----------------
__global__ __launch_bounds__(256) void stats_kernel() {
    int o = threadIdx.x;
    int base = blockIdx.x * 128;
    float s = 0.f, q = 0.f;
    const float* p = g_y + (size_t)base * 256 + o;
    for (int i = 0; i < 128; i++) {
        float v = p[(size_t)i * 256];
        s += v;
        q = fmaf(v, v, q);
    }
    atomicAdd(&g_sum[o], s);
    atomicAdd(&g_sq[o], q);
}

// ---------------- kernel 6: finalize scale/shift ----------------
__global__ void finalize_kernel(const float* __restrict__ gamma,
                                const float* __restrict__ beta) {
    int o = threadIdx.x;
    const float inv_n = 1.f / (float)NHW;
    float m = g_sum[o] * inv_n;
    float v = g_sq[o] * inv_n - m * m;
    float a = v + 1e-5f;
    float is = rsqrtf(a);
    is = is * (1.5f - 0.5f * a * is * is);
    float sc = is * gamma[o];
    g_scale[o] = sc;
    g_shift[o] = beta[o] - m * sc;
}

// ---------------- kernel 7: BN + ReLU + transpose to NCHW ----------------
__global__ __launch_bounds__(256) void bn_relu_kernel(float* __restrict__ out) {
    __shared__ float t[32][33];
    int gp0 = blockIdx.x * 32;
    int o0  = blockIdx.y * 32;
    int tx = threadIdx.x & 31, ty = threadIdx.x >> 5;
    int n  = gp0 / HW;
    int lp0 = gp0 - n * HW;
#pragma unroll
    for (int j = 0; j < 4; j++) {
        int pr = ty + j * 8;
        t[pr][tx] = g_y[(size_t)(gp0 + pr) * 256 + o0 + tx];
    }
    __syncthreads();
#pragma unroll
    for (int j = 0; j < 4; j++) {
        int oo = o0 + ty + j * 8;
        float v = t[tx][ty + j * 8];
        v = fmaxf(fmaf(v, g_scale[oo], g_shift[oo]), 0.f);
        out[((size_t)(n * 256 + oo)) * HW + lp0 + tx] = v;
    }
}

// ---------------- launch ----------------
extern "C" void kernel_launch(void* const* d_in, const int* in_sizes, int n_in,
                              void* d_out, int out_size) {
    const float* x     = (const float*)d_in[0];
    const float* w_off = (const float*)d_in[1];
    const float* b_off = (const float*)d_in[2];
    const float* w_dcn = (const float*)d_in[3];
    const float* gamma = (const float*)d_in[4];
    const float* beta  = (const float*)d_in[5];

    cudaFuncSetAttribute(dcn_gemm_kernel,
                         cudaFuncAttributeMaxDynamicSharedMemorySize, SMEM_GEMM);

    prep_kernel<<<1152, 512>>>(w_dcn, w_off);
    offset_conv_kernel<<<dim3(6, 6, NN), 256>>>(x, b_off);
    zero_stats_kernel<<<1, 256>>>();
    dcn_gemm_kernel<<<NHW / BM, NTHR, SMEM_GEMM>>>(x);     // 288 CTAs
    stats_kernel<<<288, 256>>>();
    finalize_kernel<<<1, 256>>>(gamma, beta);
    bn_relu_kernel<<<dim3(NHW / 32, 8), 256>>>((float*)d_out);
}

// round 10
// speedup vs baseline: 2.1992x; 1.0655x over previous
#include <cuda_runtime.h>
#include <cuda_bf16.h>
#include <cstdint>

#define NN   4
#define CC   256
#define OO   256
#define HH   96
#define WW   96
#define HW   9216
#define NHW  36864

#define BM   128
#define NTHR 512
#define NCHUNK 72           // 9 taps (inner) x 8 c-subchunks (outer)

// GEMM smem (bytes). Tiles use 80B row pitch (40 bf16): ldmatrix 8-row phases
// hit banks {0,20,8,28,16,4,24,12}*4w -> conflict-free. Two pipeline stages.
#define SM_WT    0                      // float4 [9][128]  = 18432
#define SM_IT    18432                  // ushort4[9][128]  =  9216
#define SM_ST0   27648
#define STAGE_SZ 61440                  // AH 10240 | AL 10240 | BH 20480 | BL 20480
#define O_AH 0
#define O_AL 10240
#define O_BH 20480
#define O_BL 40960
#define SMEM_GEMM (SM_ST0 + 2*STAGE_SZ) // 150528

// ---- scratch globals ----
__device__ __align__(256) float         g_off[NN * 18 * HW];
__device__ __align__(256) __nv_bfloat16 g_Bh[OO * 2304];
__device__ __align__(256) __nv_bfloat16 g_Bl[OO * 2304];
__device__ __align__(256) float2        g_wo2[CC * 81];
__device__ __align__(256) float         g_y[NHW * 256];   // pixel-major [gpix][o]
__device__ float g_sum[OO];
__device__ float g_sq[OO];
__device__ float g_scale[OO];
__device__ float g_shift[OO];

// ---- helpers ----
__device__ __forceinline__ uint32_t smem_addr(const void* p) {
    uint32_t a;
    asm("{ .reg .u64 t; cvta.to.shared.u64 t, %1; cvt.u32.u64 %0, t; }" : "=r"(a) : "l"(p));
    return a;
}
__device__ __forceinline__ void cpa16(uint32_t d, const void* s) {
    asm volatile("cp.async.cg.shared.global [%0], [%1], 16;" :: "r"(d), "l"(s) : "memory");
}
__device__ __forceinline__ void cpa8(uint32_t d, const void* s) {
    asm volatile("cp.async.ca.shared.global [%0], [%1], 8;" :: "r"(d), "l"(s) : "memory");
}
__device__ __forceinline__ void cpa4z(uint32_t d, const void* s, int sz) {
    asm volatile("cp.async.ca.shared.global [%0], [%1], 4, %2;" :: "r"(d), "l"(s), "r"(sz) : "memory");
}
__device__ __forceinline__ void cpa_commit() {
    asm volatile("cp.async.commit_group;" ::: "memory");
}
__device__ __forceinline__ void cpa_wait0() {
    asm volatile("cp.async.wait_group 0;" ::: "memory");
}
__device__ __forceinline__ void ldsm4(uint32_t &r0, uint32_t &r1, uint32_t &r2, uint32_t &r3,
                                      uint32_t addr) {
    asm volatile("ldmatrix.sync.aligned.m8n8.x4.shared.b16 {%0,%1,%2,%3}, [%4];"
                 : "=r"(r0), "=r"(r1), "=r"(r2), "=r"(r3) : "r"(addr));
}
__device__ __forceinline__ uint32_t pkbf(__nv_bfloat16 a, __nv_bfloat16 b) {
    return (uint32_t)__bfloat16_as_ushort(a) | ((uint32_t)__bfloat16_as_ushort(b) << 16);
}
__device__ __forceinline__ unsigned long long pack2(float x, float y) {
    unsigned long long r;
    asm("mov.b64 %0, {%1, %2};" : "=l"(r) : "f"(x), "f"(y));
    return r;
}
__device__ __forceinline__ void unpack2(unsigned long long v, float &x, float &y) {
    asm("mov.b64 {%0, %1}, %2;" : "=f"(x), "=f"(y) : "l"(v));
}
__device__ __forceinline__ void ffma2(unsigned long long &d, unsigned long long a,
                                      unsigned long long b) {
    asm("fma.rn.f32x2 %0, %1, %2, %0;" : "+l"(d) : "l"(a), "l"(b));
}
__device__ __forceinline__ void mma_bf16(float* d, const uint32_t* a,
                                         uint32_t b0, uint32_t b1) {
    asm volatile(
        "mma.sync.aligned.m16n8k16.row.col.f32.bf16.bf16.f32 "
        "{%0,%1,%2,%3}, {%4,%5,%6,%7}, {%8,%9}, {%0,%1,%2,%3};"
        : "+f"(d[0]), "+f"(d[1]), "+f"(d[2]), "+f"(d[3])
        : "r"(a[0]), "r"(a[1]), "r"(a[2]), "r"(a[3]), "r"(b0), "r"(b1));
}

// ---------------- kernel 1: weight prep ----------------
__global__ void prep_kernel(const float* __restrict__ w_dcn,
                            const float* __restrict__ w_off) {
    int e = blockIdx.x * blockDim.x + threadIdx.x;   // 589824 exact
    {
        int o = e / 2304, r = e - o * 2304;
        int kt = r >> 8, c = r & 255;
        float v = w_dcn[(o * CC + c) * 9 + kt];
        __nv_bfloat16 hi = __float2bfloat16(v);
        g_Bh[e] = hi;
        g_Bl[e] = __float2bfloat16(v - __bfloat162float(hi));
    }
    if (e < CC * 81) {
        int c = e / 81, r = e - c * 81;
        int t = r / 9, p = r - t * 9;
        g_wo2[e] = make_float2(w_off[(2 * p) * 2304 + c * 9 + t],
                               w_off[(2 * p + 1) * 2304 + c * 9 + t]);
    }
}

// ---------------- kernel 2: offset conv, cp.async double-buffered ----------------
__global__ __launch_bounds__(256) void offset_conv_kernel(
    const float* __restrict__ x, const float* __restrict__ b_off)
{
    __shared__ float xs[2][4][18][19];
    __shared__ unsigned long long ws[2][4][81];
    int n  = blockIdx.z;
    int h0 = blockIdx.y * 16, w0 = blockIdx.x * 16;
    int tid = threadIdx.x;
    int ty = tid >> 4, tx = tid & 15;
    uint32_t xs_b = smem_addr(&xs[0][0][0][0]);
    uint32_t ws_b = smem_addr(&ws[0][0][0]);
    const unsigned long long* wo2 = (const unsigned long long*)g_wo2;

    unsigned long long acc[9];
#pragma unroll
    for (int p = 0; p < 9; p++) acc[p] = 0ull;

    auto prefetch = [&](int cg, int st) {
        int cb = cg * 4;
        for (int i = tid; i < 1296; i += 256) {
            int cl = i / 324, r2 = i - cl * 324;
            int r = r2 / 18, q = r2 - r * 18;
            int hh = h0 - 1 + r, wp = w0 - 1 + q;
            int ok = ((unsigned)hh < (unsigned)HH && (unsigned)wp < (unsigned)WW) ? 4 : 0;
            int hc = min(max(hh, 0), HH - 1), wc = min(max(wp, 0), WW - 1);
            cpa4z(xs_b + (uint32_t)(((st * 4 + cl) * 342) + r * 19 + q) * 4,
                  &x[((n * CC + cb + cl) * HH + hc) * WW + wc], ok);
        }
        for (int i = tid; i < 324; i += 256) {
            int cl = i / 81, r = i - cl * 81;
            cpa8(ws_b + (uint32_t)((st * 4 + cl) * 81 + r) * 8, &wo2[(cb + cl) * 81 + r]);
        }
        cpa_commit();
    };

    prefetch(0, 0);
    cpa_wait0();
    __syncthreads();

    for (int cg = 0; cg < 64; cg++) {
        int st = cg & 1;
        if (cg < 63) prefetch(cg + 1, st ^ 1);
#pragma unroll
        for (int cl = 0; cl < 4; cl++) {
            float xv[9];
#pragma unroll
            for (int t = 0; t < 9; t++) xv[t] = xs[st][cl][ty + t / 3][tx + t % 3];
#pragma unroll
            for (int t = 0; t < 9; t++) {
                unsigned long long bb = pack2(xv[t], xv[t]);
#pragma unroll
                for (int p = 0; p < 9; p++) ffma2(acc[p], ws[st][cl][t * 9 + p], bb);
            }
        }
        cpa_wait0();
        __syncthreads();
    }
    int h = h0 + ty, w = w0 + tx;
#pragma unroll
    for (int p = 0; p < 9; p++) {
        float a0, a1;
        unpack2(acc[p], a0, a1);
        g_off[((n * 18 + 2 * p) * HH + h) * WW + w]     = a0 + b_off[2 * p];
        g_off[((n * 18 + 2 * p + 1) * HH + h) * WW + w] = a1 + b_off[2 * p + 1];
    }
}

// ---------------- kernel 3: zero BN accumulators ----------------
__global__ void zero_stats_kernel() {
    g_sum[threadIdx.x] = 0.f;
    g_sq[threadIdx.x]  = 0.f;
}

// ---------------- kernel 4: HMMA GEMM, ldmatrix + 2-stage pipeline ----------------
__global__ __launch_bounds__(NTHR, 1) void dcn_gemm_kernel(const float* __restrict__ X)
{
    extern __shared__ __align__(128) char smem[];
    float4*  wt = (float4*)(smem + SM_WT);
    ushort4* it = (ushort4*)(smem + SM_IT);
    uint32_t sb = smem_addr(smem);

    int tid = threadIdx.x;
    int wid = tid >> 5, lid = tid & 31;
    int m0   = blockIdx.x * BM;
    int n    = m0 / HW;
    int pix0 = m0 - n * HW;

    // ---- bilinear tables ----
    for (int e = tid; e < BM * 9; e += NTHR) {
        int k = e / BM, mi = e - k * BM;
        int pix = pix0 + mi;
        int h = pix / WW, w = pix - h * WW;
        float dy = g_off[((n * 18 + 2 * k) * HH + h) * WW + w];
        float dx = g_off[((n * 18 + 2 * k + 1) * HH + h) * WW + w];
        float py = (float)(h + k / 3 - 1) + dy;
        float px = (float)(w + (k % 3) - 1) + dx;
        float fy = floorf(py), fx = floorf(px);
        int y0 = (int)fy, x0 = (int)fx;
        float wy = py - fy, wx = px - fx;
        float m00 = ((unsigned)y0 < HH && (unsigned)x0 < WW) ? 1.f : 0.f;
        float m01 = ((unsigned)y0 < HH && (unsigned)(x0 + 1) < WW) ? 1.f : 0.f;
        float m10 = ((unsigned)(y0 + 1) < HH && (unsigned)x0 < WW) ? 1.f : 0.f;
        float m11 = ((unsigned)(y0 + 1) < HH && (unsigned)(x0 + 1) < WW) ? 1.f : 0.f;
        int yc0 = min(max(y0, 0), HH - 1), yc1 = min(max(y0 + 1, 0), HH - 1);
        int xc0 = min(max(x0, 0), WW - 1), xc1 = min(max(x0 + 1, 0), WW - 1);
        wt[e] = make_float4((1.f - wy) * (1.f - wx) * m00, (1.f - wy) * wx * m01,
                            wy * (1.f - wx) * m10, wy * wx * m11);
        it[e] = make_ushort4((unsigned short)(yc0 * WW + xc0), (unsigned short)(yc0 * WW + xc1),
                             (unsigned short)(yc1 * WW + xc0), (unsigned short)(yc1 * WW + xc1));
    }
    __syncthreads();

    float acc[2][8][4];
#pragma unroll
    for (int a = 0; a < 2; a++)
#pragma unroll
        for (int b = 0; b < 8; b++)
#pragma unroll
            for (int c = 0; c < 4; c++) acc[a][b][c] = 0.f;

    int wm = wid & 3, wn = wid >> 2;
    int bRow = tid >> 1, bHalf = tid & 1;
    int aCh  = wid * 2;
    const float* xn = X + (size_t)n * CC * HW;

    // ldmatrix lane-address offsets (within a tile, before AOFF/BOFF/stage)
    // A x4: {rows0-7 k0-7, rows8-15 k0-7, rows0-7 k8-15, rows8-15 k8-15}
    uint32_t aLane = (uint32_t)((wm * 32 + ((lid >> 3) & 1) * 8 + (lid & 7)) * 80 + (lid >> 4) * 16);
    // B x4: {ntE k0-7, ntE k8-15, ntO k0-7, ntO k8-15} for an nt pair
    uint32_t bLane = (uint32_t)((wn * 64 + ((lid >> 4) & 1) * 8 + (lid & 7)) * 80 + ((lid >> 3) & 1) * 16);

    // B cp.async for chunk (kt, c0) into stage base stN
    auto b_prefetch = [&](int kt, int c0, uint32_t stN) {
        const char* srcH = (const char*)(g_Bh + (size_t)bRow * 2304 + kt * 256 + c0 + bHalf * 16);
        const char* srcL = (const char*)(g_Bl + (size_t)bRow * 2304 + kt * 256 + c0 + bHalf * 16);
        uint32_t dH = sb + stN + O_BH + bRow * 80 + bHalf * 32;
        uint32_t dL = sb + stN + O_BL + bRow * 80 + bHalf * 32;
        cpa16(dH, srcH); cpa16(dH + 16, srcH + 16);
        cpa16(dL, srcL); cpa16(dL + 16, srcL + 16);
        cpa_commit();
    };
    auto a_store = [&](uint32_t stN, int mi, float4 w4, const float* va) {
        float v0 = w4.x * va[0] + w4.y * va[1] + w4.z * va[2] + w4.w * va[3];
        float v1 = w4.x * va[4] + w4.y * va[5] + w4.z * va[6] + w4.w * va[7];
        __nv_bfloat16 h0 = __float2bfloat16(v0);
        __nv_bfloat16 h1 = __float2bfloat16(v1);
        uint32_t off = mi * 80 + aCh * 2;
        *(uint32_t*)(smem + stN + O_AH + off) = pkbf(h0, h1);
        *(uint32_t*)(smem + stN + O_AL + off) =
            pkbf(__float2bfloat16(v0 - __bfloat162float(h0)),
                 __float2bfloat16(v1 - __bfloat162float(h1)));
    };
    // one MMA term over stage stS, ldmatrix fragments
    auto mma_term = [&](uint32_t stS, int AOFF, int BOFF) {
        uint32_t aB = sb + stS + AOFF + aLane;
        uint32_t bB = sb + stS + BOFF + bLane;
#pragma unroll
        for (int ks = 0; ks < 2; ks++) {
            uint32_t a0[4], a1[4];
            ldsm4(a0[0], a0[1], a0[2], a0[3], aB + ks * 32);
            ldsm4(a1[0], a1[1], a1[2], a1[3], aB + 16 * 80 + ks * 32);
#pragma unroll
            for (int np = 0; np < 4; np++) {
                uint32_t b[4];
                ldsm4(b[0], b[1], b[2], b[3], bB + np * 16 * 80 + ks * 32);
                mma_bf16(acc[0][np * 2],     a0, b[0], b[1]);
                mma_bf16(acc[1][np * 2],     a1, b[0], b[1]);
                mma_bf16(acc[0][np * 2 + 1], a0, b[2], b[3]);
                mma_bf16(acc[1][np * 2 + 1], a1, b[2], b[3]);
            }
        }
    };

    // chunk -> (kt inner, c outer): gather footprint stays L1-resident for 9 chunks
    // ---- prologue: chunk 0 (kt=0, c0=0) ----
    b_prefetch(0, 0, SM_ST0);
    {
        const float* xb0 = xn + (size_t)aCh * HW;
#pragma unroll
        for (int rg = 0; rg < 4; rg++) {
            int mi = (rg << 5) + lid;
            float4  w4 = wt[mi];
            ushort4 i4 = it[mi];
            float va[8];
            va[0] = xb0[i4.x]; va[1] = xb0[i4.y]; va[2] = xb0[i4.z]; va[3] = xb0[i4.w];
            const float* xb1 = xb0 + HW;
            va[4] = xb1[i4.x]; va[5] = xb1[i4.y]; va[6] = xb1[i4.z]; va[7] = xb1[i4.w];
            a_store(SM_ST0, mi, w4, va);
        }
    }
    cpa_wait0();
    __syncthreads();

    for (int ch = 0; ch < NCHUNK; ch++) {
        uint32_t stS = SM_ST0 + (uint32_t)(ch & 1) * STAGE_SZ;
        uint32_t stN = SM_ST0 + (uint32_t)((ch & 1) ^ 1) * STAGE_SZ;
        bool pf = (ch + 1 < NCHUNK);
        int ch2 = ch + 1;
        int c2i = ch2 / 9;
        int kt2 = ch2 - c2i * 9, c02 = c2i * 32;

        if (pf) b_prefetch(kt2, c02, stN);

        float va[16];
        float4 w40, w41;
        int mi0 = lid, mi1 = 32 + lid;
        const float* xb0 = xn + (size_t)(c02 + aCh) * HW;
        if (pf) {
            w40 = wt[kt2 * BM + mi0];
            ushort4 i40 = it[kt2 * BM + mi0];
            va[0] = xb0[i40.x]; va[1] = xb0[i40.y]; va[2] = xb0[i40.z]; va[3] = xb0[i40.w];
            const float* xb1 = xb0 + HW;
            va[4] = xb1[i40.x]; va[5] = xb1[i40.y]; va[6] = xb1[i40.z]; va[7] = xb1[i40.w];
            w41 = wt[kt2 * BM + mi1];
            ushort4 i41 = it[kt2 * BM + mi1];
            va[8]  = xb0[i41.x]; va[9]  = xb0[i41.y]; va[10] = xb0[i41.z]; va[11] = xb0[i41.w];
            va[12] = xb1[i41.x]; va[13] = xb1[i41.y]; va[14] = xb1[i41.z]; va[15] = xb1[i41.w];
        }

        mma_term(stS, O_AH, O_BH);

        if (pf) {
            a_store(stN, mi0, w40, va);
            a_store(stN, mi1, w41, va + 8);
            int mi2 = 64 + lid, mi3 = 96 + lid;
            w40 = wt[kt2 * BM + mi2];
            ushort4 i42 = it[kt2 * BM + mi2];
            va[0] = xb0[i42.x]; va[1] = xb0[i42.y]; va[2] = xb0[i42.z]; va[3] = xb0[i42.w];
            const float* xb1 = xb0 + HW;
            va[4] = xb1[i42.x]; va[5] = xb1[i42.y]; va[6] = xb1[i42.z]; va[7] = xb1[i42.w];
            w41 = wt[kt2 * BM + mi3];
            ushort4 i43 = it[kt2 * BM + mi3];
            va[8]  = xb0[i43.x]; va[9]  = xb0[i43.y]; va[10] = xb0[i43.z]; va[11] = xb0[i43.w];
            va[12] = xb1[i43.x]; va[13] = xb1[i43.y]; va[14] = xb1[i43.z]; va[15] = xb1[i43.w];
        }

        mma_term(stS, O_AH, O_BL);

        if (pf) {
            a_store(stN, 64 + lid, w40, va);
            a_store(stN, 96 + lid, w41, va + 8);
        }

        mma_term(stS, O_AL, O_BH);

        cpa_wait0();
        __syncthreads();
    }

    // ---- epilogue: D frags -> g_y[gpix][o] ----
    float* yb = g_y + (size_t)m0 * 256;
    int g = lid >> 2, c4 = lid & 3;
#pragma unroll
    for (int mt = 0; mt < 2; mt++) {
        int pr = wm * 32 + mt * 16 + g;
#pragma unroll
        for (int nt = 0; nt < 8; nt++) {
            int oc = wn * 64 + nt * 8 + c4 * 2;
            *(float2*)(yb + (size_t)pr * 256 + oc) =
                make_float2(acc[mt][nt][0], acc[mt][nt][1]);
            *(float2*)(yb + (size_t)(pr + 8) * 256 + oc) =
                make_float2(acc[mt][nt][2], acc[mt][nt][3]);
        }
    }
}

// ---------------- kernel 5: BN partial stats ----------------
__global__ __launch_bounds__(256) void stats_kernel() {
    int o = threadIdx.x;
    int base = blockIdx.x * 128;
    float s = 0.f, q = 0.f;
    const float* p = g_y + (size_t)base * 256 + o;
    for (int i = 0; i < 128; i++) {
        float v = p[(size_t)i * 256];
        s += v;
        q = fmaf(v, v, q);
    }
    atomicAdd(&g_sum[o], s);
    atomicAdd(&g_sq[o], q);
}

// ---------------- kernel 6: finalize scale/shift ----------------
__global__ void finalize_kernel(const float* __restrict__ gamma,
                                const float* __restrict__ beta) {
    int o = threadIdx.x;
    const float inv_n = 1.f / (float)NHW;
    float m = g_sum[o] * inv_n;
    float v = g_sq[o] * inv_n - m * m;
    float a = v + 1e-5f;
    float is = rsqrtf(a);
    is = is * (1.5f - 0.5f * a * is * is);
    float sc = is * gamma[o];
    g_scale[o] = sc;
    g_shift[o] = beta[o] - m * sc;
}

// ---------------- kernel 7: BN + ReLU + transpose to NCHW ----------------
__global__ __launch_bounds__(256) void bn_relu_kernel(float* __restrict__ out) {
    __shared__ float t[32][33];
    int gp0 = blockIdx.x * 32;
    int o0  = blockIdx.y * 32;
    int tx = threadIdx.x & 31, ty = threadIdx.x >> 5;
    int n  = gp0 / HW;
    int lp0 = gp0 - n * HW;
#pragma unroll
    for (int j = 0; j < 4; j++) {
        int pr = ty + j * 8;
        t[pr][tx] = g_y[(size_t)(gp0 + pr) * 256 + o0 + tx];
    }
    __syncthreads();
#pragma unroll
    for (int j = 0; j < 4; j++) {
        int oo = o0 + ty + j * 8;
        float v = t[tx][ty + j * 8];
        v = fmaxf(fmaf(v, g_scale[oo], g_shift[oo]), 0.f);
        out[((size_t)(n * 256 + oo)) * HW + lp0 + tx] = v;
    }
}

// ---------------- launch ----------------
extern "C" void kernel_launch(void* const* d_in, const int* in_sizes, int n_in,
                              void* d_out, int out_size) {
    const float* x     = (const float*)d_in[0];
    const float* w_off = (const float*)d_in[1];
    const float* b_off = (const float*)d_in[2];
    const float* w_dcn = (const float*)d_in[3];
    const float* gamma = (const float*)d_in[4];
    const float* beta  = (const float*)d_in[5];

    cudaFuncSetAttribute(dcn_gemm_kernel,
                         cudaFuncAttributeMaxDynamicSharedMemorySize, SMEM_GEMM);

    prep_kernel<<<1152, 512>>>(w_dcn, w_off);
    offset_conv_kernel<<<dim3(6, 6, NN), 256>>>(x, b_off);
    zero_stats_kernel<<<1, 256>>>();
    dcn_gemm_kernel<<<NHW / BM, NTHR, SMEM_GEMM>>>(x);     // 288 CTAs
    stats_kernel<<<288, 256>>>();
    finalize_kernel<<<1, 256>>>(gamma, beta);
    bn_relu_kernel<<<dim3(NHW / 32, 8), 256>>>((float*)d_out);
}

// round 11
// speedup vs baseline: 2.2914x; 1.0419x over previous
#include <cuda_runtime.h>
#include <cuda_bf16.h>
#include <cstdint>

#define NN   4
#define CC   256
#define OO   256
#define HH   96
#define WW   96
#define HW   9216
#define NHW  36864

#define BM   128
#define NTHR 512
#define NCHUNK 72           // 9 taps (inner) x 8 c-subchunks (outer)

// GEMM smem (bytes). Tiles use 80B row pitch (40 bf16): ldmatrix 8-row phases
// hit banks {0,20,8,28,16,4,24,12}*4w -> conflict-free. Two pipeline stages.
#define SM_WT    0                      // float4 [9][128]  = 18432
#define SM_IT    18432                  // ushort4[9][128]  =  9216
#define SM_ST0   27648
#define STAGE_SZ 61440                  // AH 10240 | AL 10240 | BH 20480 | BL 20480
#define O_AH 0
#define O_AL 10240
#define O_BH 20480
#define O_BL 40960
#define SMEM_GEMM (SM_ST0 + 2*STAGE_SZ) // 150528

// ---- scratch globals ----
__device__ __align__(256) float         g_off[NN * 18 * HW];
__device__ __align__(256) __nv_bfloat16 g_Bh[OO * 2304];
__device__ __align__(256) __nv_bfloat16 g_Bl[OO * 2304];
__device__ __align__(256) float2        g_wo2[CC * 81];
__device__ __align__(256) float         g_xt[(size_t)NN * HW * 256];  // pixel-major x
__device__ __align__(256) float         g_y[(size_t)NHW * 256];       // [gpix][o]
__device__ float g_sum[OO];
__device__ float g_sq[OO];
__device__ float g_scale[OO];
__device__ float g_shift[OO];

// ---- helpers ----
__device__ __forceinline__ uint32_t smem_addr(const void* p) {
    uint32_t a;
    asm("{ .reg .u64 t; cvta.to.shared.u64 t, %1; cvt.u32.u64 %0, t; }" : "=r"(a) : "l"(p));
    return a;
}
__device__ __forceinline__ void cpa16(uint32_t d, const void* s) {
    asm volatile("cp.async.cg.shared.global [%0], [%1], 16;" :: "r"(d), "l"(s) : "memory");
}
__device__ __forceinline__ void cpa8(uint32_t d, const void* s) {
    asm volatile("cp.async.ca.shared.global [%0], [%1], 8;" :: "r"(d), "l"(s) : "memory");
}
__device__ __forceinline__ void cpa4z(uint32_t d, const void* s, int sz) {
    asm volatile("cp.async.ca.shared.global [%0], [%1], 4, %2;" :: "r"(d), "l"(s), "r"(sz) : "memory");
}
__device__ __forceinline__ void cpa_commit() {
    asm volatile("cp.async.commit_group;" ::: "memory");
}
__device__ __forceinline__ void cpa_wait0() {
    asm volatile("cp.async.wait_group 0;" ::: "memory");
}
__device__ __forceinline__ void ldsm4(uint32_t &r0, uint32_t &r1, uint32_t &r2, uint32_t &r3,
                                      uint32_t addr) {
    asm volatile("ldmatrix.sync.aligned.m8n8.x4.shared.b16 {%0,%1,%2,%3}, [%4];"
                 : "=r"(r0), "=r"(r1), "=r"(r2), "=r"(r3) : "r"(addr));
}
__device__ __forceinline__ uint32_t pkbf(__nv_bfloat16 a, __nv_bfloat16 b) {
    return (uint32_t)__bfloat16_as_ushort(a) | ((uint32_t)__bfloat16_as_ushort(b) << 16);
}
__device__ __forceinline__ unsigned long long pack2(float x, float y) {
    unsigned long long r;
    asm("mov.b64 %0, {%1, %2};" : "=l"(r) : "f"(x), "f"(y));
    return r;
}
__device__ __forceinline__ void unpack2(unsigned long long v, float &x, float &y) {
    asm("mov.b64 {%0, %1}, %2;" : "=f"(x), "=f"(y) : "l"(v));
}
__device__ __forceinline__ void ffma2(unsigned long long &d, unsigned long long a,
                                      unsigned long long b) {
    asm("fma.rn.f32x2 %0, %1, %2, %0;" : "+l"(d) : "l"(a), "l"(b));
}
__device__ __forceinline__ void mma_bf16(float* d, const uint32_t* a,
                                         uint32_t b0, uint32_t b1) {
    asm volatile(
        "mma.sync.aligned.m16n8k16.row.col.f32.bf16.bf16.f32 "
        "{%0,%1,%2,%3}, {%4,%5,%6,%7}, {%8,%9}, {%0,%1,%2,%3};"
        : "+f"(d[0]), "+f"(d[1]), "+f"(d[2]), "+f"(d[3])
        : "r"(a[0]), "r"(a[1]), "r"(a[2]), "r"(a[3]), "r"(b0), "r"(b1));
}

// ---------------- kernel 1: weight prep ----------------
__global__ void prep_kernel(const float* __restrict__ w_dcn,
                            const float* __restrict__ w_off) {
    int e = blockIdx.x * blockDim.x + threadIdx.x;   // 589824 exact
    {
        int o = e / 2304, r = e - o * 2304;
        int kt = r >> 8, c = r & 255;
        float v = w_dcn[(o * CC + c) * 9 + kt];
        __nv_bfloat16 hi = __float2bfloat16(v);
        g_Bh[e] = hi;
        g_Bl[e] = __float2bfloat16(v - __bfloat162float(hi));
    }
    if (e < CC * 81) {
        int c = e / 81, r = e - c * 81;
        int t = r / 9, p = r - t * 9;
        g_wo2[e] = make_float2(w_off[(2 * p) * 2304 + c * 9 + t],
                               w_off[(2 * p + 1) * 2304 + c * 9 + t]);
    }
}

// ---------------- kernel 1b: transpose x -> pixel-major [n][pix][c] ----------------
__global__ __launch_bounds__(256) void transpose_kernel(const float* __restrict__ x) {
    __shared__ float t[32][33];
    int p0 = blockIdx.x * 32;
    int c0 = blockIdx.y * 32;
    int n  = blockIdx.z;
    int tx = threadIdx.x & 31, ty = threadIdx.x >> 5;
#pragma unroll
    for (int j = 0; j < 4; j++) {
        int c = c0 + ty + j * 8;
        t[ty + j * 8][tx] = x[((size_t)(n * CC + c)) * HW + p0 + tx];
    }
    __syncthreads();
#pragma unroll
    for (int j = 0; j < 4; j++) {
        int p = p0 + ty + j * 8;
        g_xt[((size_t)n * HW + p) * 256 + c0 + tx] = t[tx][ty + j * 8];
    }
}

// ---------------- kernel 2: offset conv, cp.async double-buffered ----------------
__global__ __launch_bounds__(256) void offset_conv_kernel(
    const float* __restrict__ x, const float* __restrict__ b_off)
{
    __shared__ float xs[2][4][18][19];
    __shared__ unsigned long long ws[2][4][81];
    int n  = blockIdx.z;
    int h0 = blockIdx.y * 16, w0 = blockIdx.x * 16;
    int tid = threadIdx.x;
    int ty = tid >> 4, tx = tid & 15;
    uint32_t xs_b = smem_addr(&xs[0][0][0][0]);
    uint32_t ws_b = smem_addr(&ws[0][0][0]);
    const unsigned long long* wo2 = (const unsigned long long*)g_wo2;

    unsigned long long acc[9];
#pragma unroll
    for (int p = 0; p < 9; p++) acc[p] = 0ull;

    auto prefetch = [&](int cg, int st) {
        int cb = cg * 4;
        for (int i = tid; i < 1296; i += 256) {
            int cl = i / 324, r2 = i - cl * 324;
            int r = r2 / 18, q = r2 - r * 18;
            int hh = h0 - 1 + r, wp = w0 - 1 + q;
            int ok = ((unsigned)hh < (unsigned)HH && (unsigned)wp < (unsigned)WW) ? 4 : 0;
            int hc = min(max(hh, 0), HH - 1), wc = min(max(wp, 0), WW - 1);
            cpa4z(xs_b + (uint32_t)(((st * 4 + cl) * 342) + r * 19 + q) * 4,
                  &x[((n * CC + cb + cl) * HH + hc) * WW + wc], ok);
        }
        for (int i = tid; i < 324; i += 256) {
            int cl = i / 81, r = i - cl * 81;
            cpa8(ws_b + (uint32_t)((st * 4 + cl) * 81 + r) * 8, &wo2[(cb + cl) * 81 + r]);
        }
        cpa_commit();
    };

    prefetch(0, 0);
    cpa_wait0();
    __syncthreads();

    for (int cg = 0; cg < 64; cg++) {
        int st = cg & 1;
        if (cg < 63) prefetch(cg + 1, st ^ 1);
#pragma unroll
        for (int cl = 0; cl < 4; cl++) {
            float xv[9];
#pragma unroll
            for (int t = 0; t < 9; t++) xv[t] = xs[st][cl][ty + t / 3][tx + t % 3];
#pragma unroll
            for (int t = 0; t < 9; t++) {
                unsigned long long bb = pack2(xv[t], xv[t]);
#pragma unroll
                for (int p = 0; p < 9; p++) ffma2(acc[p], ws[st][cl][t * 9 + p], bb);
            }
        }
        cpa_wait0();
        __syncthreads();
    }
    int h = h0 + ty, w = w0 + tx;
#pragma unroll
    for (int p = 0; p < 9; p++) {
        float a0, a1;
        unpack2(acc[p], a0, a1);
        g_off[((n * 18 + 2 * p) * HH + h) * WW + w]     = a0 + b_off[2 * p];
        g_off[((n * 18 + 2 * p + 1) * HH + h) * WW + w] = a1 + b_off[2 * p + 1];
    }
}

// ---------------- kernel 3: zero BN accumulators ----------------
__global__ void zero_stats_kernel() {
    g_sum[threadIdx.x] = 0.f;
    g_sq[threadIdx.x]  = 0.f;
}

// ---------------- kernel 4: HMMA GEMM, coalesced gather + ldmatrix pipeline ----
__global__ __launch_bounds__(NTHR, 1) void dcn_gemm_kernel(const float* __restrict__ X)
{
    extern __shared__ __align__(128) char smem[];
    float4*  wt = (float4*)(smem + SM_WT);
    ushort4* it = (ushort4*)(smem + SM_IT);
    uint32_t sb = smem_addr(smem);

    int tid = threadIdx.x;
    int wid = tid >> 5, lid = tid & 31;
    int m0   = blockIdx.x * BM;
    int n    = m0 / HW;
    int pix0 = m0 - n * HW;

    // ---- bilinear tables ----
    for (int e = tid; e < BM * 9; e += NTHR) {
        int k = e / BM, mi = e - k * BM;
        int pix = pix0 + mi;
        int h = pix / WW, w = pix - h * WW;
        float dy = g_off[((n * 18 + 2 * k) * HH + h) * WW + w];
        float dx = g_off[((n * 18 + 2 * k + 1) * HH + h) * WW + w];
        float py = (float)(h + k / 3 - 1) + dy;
        float px = (float)(w + (k % 3) - 1) + dx;
        float fy = floorf(py), fx = floorf(px);
        int y0 = (int)fy, x0 = (int)fx;
        float wy = py - fy, wx = px - fx;
        float m00 = ((unsigned)y0 < HH && (unsigned)x0 < WW) ? 1.f : 0.f;
        float m01 = ((unsigned)y0 < HH && (unsigned)(x0 + 1) < WW) ? 1.f : 0.f;
        float m10 = ((unsigned)(y0 + 1) < HH && (unsigned)x0 < WW) ? 1.f : 0.f;
        float m11 = ((unsigned)(y0 + 1) < HH && (unsigned)(x0 + 1) < WW) ? 1.f : 0.f;
        int yc0 = min(max(y0, 0), HH - 1), yc1 = min(max(y0 + 1, 0), HH - 1);
        int xc0 = min(max(x0, 0), WW - 1), xc1 = min(max(x0 + 1, 0), WW - 1);
        wt[e] = make_float4((1.f - wy) * (1.f - wx) * m00, (1.f - wy) * wx * m01,
                            wy * (1.f - wx) * m10, wy * wx * m11);
        it[e] = make_ushort4((unsigned short)(yc0 * WW + xc0), (unsigned short)(yc0 * WW + xc1),
                             (unsigned short)(yc1 * WW + xc0), (unsigned short)(yc1 * WW + xc1));
    }
    __syncthreads();

    float acc[2][8][4];
#pragma unroll
    for (int a = 0; a < 2; a++)
#pragma unroll
        for (int b = 0; b < 8; b++)
#pragma unroll
            for (int c = 0; c < 4; c++) acc[a][b][c] = 0.f;

    int wm = wid & 3, wn = wid >> 2;
    int bRow = tid >> 1, bHalf = tid & 1;
    int half = lid >> 4;            // which pixel of the pair
    int cl2  = (lid & 15) << 1;     // channel pair within 32-chunk
    const float* xtn = g_xt + (size_t)n * HW * 256;

    // ldmatrix lane-address offsets (within a tile)
    uint32_t aLane = (uint32_t)((wm * 32 + ((lid >> 3) & 1) * 8 + (lid & 7)) * 80 + (lid >> 4) * 16);
    uint32_t bLane = (uint32_t)((wn * 64 + ((lid >> 4) & 1) * 8 + (lid & 7)) * 80 + ((lid >> 3) & 1) * 16);

    auto b_prefetch = [&](int kt, int c0, uint32_t stN) {
        const char* srcH = (const char*)(g_Bh + (size_t)bRow * 2304 + kt * 256 + c0 + bHalf * 16);
        const char* srcL = (const char*)(g_Bl + (size_t)bRow * 2304 + kt * 256 + c0 + bHalf * 16);
        uint32_t dH = sb + stN + O_BH + bRow * 80 + bHalf * 32;
        uint32_t dL = sb + stN + O_BL + bRow * 80 + bHalf * 32;
        cpa16(dH, srcH); cpa16(dH + 16, srcH + 16);
        cpa16(dL, srcL); cpa16(dL + 16, srcL + 16);
        cpa_commit();
    };
    // gather: iter selects pixel pair; each lane loads float2 (2 channels) per corner
    auto gather = [&](int kt, int c0, int iter, float2* r, float4& w4, int& mi) {
        mi = (wid << 3) + (iter << 1) + half;
        w4 = wt[kt * BM + mi];
        ushort4 i4 = it[kt * BM + mi];
        const float* xt = xtn + c0 + cl2;
        r[0] = *(const float2*)(xt + (size_t)i4.x * 256);
        r[1] = *(const float2*)(xt + (size_t)i4.y * 256);
        r[2] = *(const float2*)(xt + (size_t)i4.z * 256);
        r[3] = *(const float2*)(xt + (size_t)i4.w * 256);
    };
    auto a_put = [&](uint32_t stN, int mi, float4 w4, const float2* r) {
        float v0 = fmaf(w4.x, r[0].x, fmaf(w4.y, r[1].x, fmaf(w4.z, r[2].x, w4.w * r[3].x)));
        float v1 = fmaf(w4.x, r[0].y, fmaf(w4.y, r[1].y, fmaf(w4.z, r[2].y, w4.w * r[3].y)));
        __nv_bfloat16 h0 = __float2bfloat16(v0);
        __nv_bfloat16 h1 = __float2bfloat16(v1);
        uint32_t off = (uint32_t)(mi * 80) + (uint32_t)(cl2 << 1);
        *(uint32_t*)(smem + stN + O_AH + off) = pkbf(h0, h1);
        *(uint32_t*)(smem + stN + O_AL + off) =
            pkbf(__float2bfloat16(v0 - __bfloat162float(h0)),
                 __float2bfloat16(v1 - __bfloat162float(h1)));
    };
    // MMA for one k-step: hoisted A frags, 3 terms
    auto mma_ks = [&](uint32_t stS, int ks) {
        uint32_t aB = sb + stS + aLane + ks * 32;
        uint32_t ah0[4], ah1[4], al0[4], al1[4];
        ldsm4(ah0[0], ah0[1], ah0[2], ah0[3], aB + O_AH);
        ldsm4(ah1[0], ah1[1], ah1[2], ah1[3], aB + O_AH + 16 * 80);
        ldsm4(al0[0], al0[1], al0[2], al0[3], aB + O_AL);
        ldsm4(al1[0], al1[1], al1[2], al1[3], aB + O_AL + 16 * 80);
        uint32_t bB = sb + stS + bLane + ks * 32;
#pragma unroll
        for (int np = 0; np < 4; np++) {
            uint32_t bh[4], bl[4];
            ldsm4(bh[0], bh[1], bh[2], bh[3], bB + O_BH + np * 16 * 80);
            ldsm4(bl[0], bl[1], bl[2], bl[3], bB + O_BL + np * 16 * 80);
            mma_bf16(acc[0][np * 2],     ah0, bh[0], bh[1]);
            mma_bf16(acc[1][np * 2],     ah1, bh[0], bh[1]);
            mma_bf16(acc[0][np * 2 + 1], ah0, bh[2], bh[3]);
            mma_bf16(acc[1][np * 2 + 1], ah1, bh[2], bh[3]);
            mma_bf16(acc[0][np * 2],     ah0, bl[0], bl[1]);
            mma_bf16(acc[1][np * 2],     ah1, bl[0], bl[1]);
            mma_bf16(acc[0][np * 2 + 1], ah0, bl[2], bl[3]);
            mma_bf16(acc[1][np * 2 + 1], ah1, bl[2], bl[3]);
            mma_bf16(acc[0][np * 2],     al0, bh[0], bh[1]);
            mma_bf16(acc[1][np * 2],     al1, bh[0], bh[1]);
            mma_bf16(acc[0][np * 2 + 1], al0, bh[2], bh[3]);
            mma_bf16(acc[1][np * 2 + 1], al1, bh[2], bh[3]);
        }
    };

    // ---- prologue: chunk 0 (kt=0, c0=0) ----
    b_prefetch(0, 0, SM_ST0);
#pragma unroll
    for (int iter = 0; iter < 4; iter++) {
        float2 r[4]; float4 w4; int mi;
        gather(0, 0, iter, r, w4, mi);
        a_put(SM_ST0, mi, w4, r);
    }
    cpa_wait0();
    __syncthreads();

    for (int ch = 0; ch < NCHUNK; ch++) {
        uint32_t stS = SM_ST0 + (uint32_t)(ch & 1) * STAGE_SZ;
        uint32_t stN = SM_ST0 + (uint32_t)((ch & 1) ^ 1) * STAGE_SZ;
        bool pf = (ch + 1 < NCHUNK);
        int ch2 = ch + 1;
        int c2i = ch2 / 9;
        int kt2 = ch2 - c2i * 9, c02 = c2i * 32;

        if (pf) b_prefetch(kt2, c02, stN);

        float2 r0[4], r1[4];
        float4 w40, w41;
        int mi0 = 0, mi1 = 0;
        if (pf) {
            gather(kt2, c02, 0, r0, w40, mi0);
            gather(kt2, c02, 1, r1, w41, mi1);
        }

        mma_ks(stS, 0);

        if (pf) {
            a_put(stN, mi0, w40, r0);
            a_put(stN, mi1, w41, r1);
            gather(kt2, c02, 2, r0, w40, mi0);
            gather(kt2, c02, 3, r1, w41, mi1);
        }

        mma_ks(stS, 1);

        if (pf) {
            a_put(stN, mi0, w40, r0);
            a_put(stN, mi1, w41, r1);
        }

        cpa_wait0();
        __syncthreads();
    }

    // ---- epilogue: D frags -> g_y[gpix][o] ----
    float* yb = g_y + (size_t)m0 * 256;
    int g = lid >> 2, c4 = lid & 3;
#pragma unroll
    for (int mt = 0; mt < 2; mt++) {
        int pr = wm * 32 + mt * 16 + g;
#pragma unroll
        for (int nt = 0; nt < 8; nt++) {
            int oc = wn * 64 + nt * 8 + c4 * 2;
            *(float2*)(yb + (size_t)pr * 256 + oc) =
                make_float2(acc[mt][nt][0], acc[mt][nt][1]);
            *(float2*)(yb + (size_t)(pr + 8) * 256 + oc) =
                make_float2(acc[mt][nt][2], acc[mt][nt][3]);
        }
    }
}

// ---------------- kernel 5: BN partial stats ----------------
__global__ __launch_bounds__(256) void stats_kernel() {
    int o = threadIdx.x;
    int base = blockIdx.x * 128;
    float s = 0.f, q = 0.f;
    const float* p = g_y + (size_t)base * 256 + o;
    for (int i = 0; i < 128; i++) {
        float v = p[(size_t)i * 256];
        s += v;
        q = fmaf(v, v, q);
    }
    atomicAdd(&g_sum[o], s);
    atomicAdd(&g_sq[o], q);
}

// ---------------- kernel 6: finalize scale/shift ----------------
__global__ void finalize_kernel(const float* __restrict__ gamma,
                                const float* __restrict__ beta) {
    int o = threadIdx.x;
    const float inv_n = 1.f / (float)NHW;
    float m = g_sum[o] * inv_n;
    float v = g_sq[o] * inv_n - m * m;
    float a = v + 1e-5f;
    float is = rsqrtf(a);
    is = is * (1.5f - 0.5f * a * is * is);
    float sc = is * gamma[o];
    g_scale[o] = sc;
    g_shift[o] = beta[o] - m * sc;
}

// ---------------- kernel 7: BN + ReLU + transpose to NCHW ----------------
__global__ __launch_bounds__(256) void bn_relu_kernel(float* __restrict__ out) {
    __shared__ float t[32][33];
    int gp0 = blockIdx.x * 32;
    int o0  = blockIdx.y * 32;
    int tx = threadIdx.x & 31, ty = threadIdx.x >> 5;
    int n  = gp0 / HW;
    int lp0 = gp0 - n * HW;
#pragma unroll
    for (int j = 0; j < 4; j++) {
        int pr = ty + j * 8;
        t[pr][tx] = g_y[(size_t)(gp0 + pr) * 256 + o0 + tx];
    }
    __syncthreads();
#pragma unroll
    for (int j = 0; j < 4; j++) {
        int oo = o0 + ty + j * 8;
        float v = t[tx][ty + j * 8];
        v = fmaxf(fmaf(v, g_scale[oo], g_shift[oo]), 0.f);
        out[((size_t)(n * 256 + oo)) * HW + lp0 + tx] = v;
    }
}

// ---------------- launch ----------------
extern "C" void kernel_launch(void* const* d_in, const int* in_sizes, int n_in,
                              void* d_out, int out_size) {
    const float* x     = (const float*)d_in[0];
    const float* w_off = (const float*)d_in[1];
    const float* b_off = (const float*)d_in[2];
    const float* w_dcn = (const float*)d_in[3];
    const float* gamma = (const float*)d_in[4];
    const float* beta  = (const float*)d_in[5];

    cudaFuncSetAttribute(dcn_gemm_kernel,
                         cudaFuncAttributeMaxDynamicSharedMemorySize, SMEM_GEMM);

    prep_kernel<<<1152, 512>>>(w_dcn, w_off);
    transpose_kernel<<<dim3(HW / 32, CC / 32, NN), 256>>>(x);
    offset_conv_kernel<<<dim3(6, 6, NN), 256>>>(x, b_off);
    zero_stats_kernel<<<1, 256>>>();
    dcn_gemm_kernel<<<NHW / BM, NTHR, SMEM_GEMM>>>(x);     // 288 CTAs
    stats_kernel<<<288, 256>>>();
    finalize_kernel<<<1, 256>>>(gamma, beta);
    bn_relu_kernel<<<dim3(NHW / 32, 8), 256>>>((float*)d_out);
}